// round 2
// baseline (speedup 1.0000x reference)
#include <cuda_runtime.h>
#include <cstdint>

#define TILE_B 64
#define W1PAD 65     // [256][65] for W1 (row-major [h][k])
#define W2PAD 257    // [64][257] for W2 (row-major [o][k])
#define XSPAD 66     // xsT [64 k][66] (samples contiguous, float2-aligned rows)
#define HPAD  66     // hT [256 k][66]

// shared-memory float offsets
#define OFF_W    0
#define N_W      16640                    // max(256*65, 64*257)
#define OFF_XS   (OFF_W + N_W)            // 16640
#define N_XS     (64 * XSPAD)             // 4224
#define OFF_H    (OFF_XS + N_XS)          // 20864
#define N_H      (256 * HPAD)             // 16896
#define OFF_ES   (OFF_H + N_H)            // 37760
#define SMEM_FLOATS (OFF_ES + 64)         // 37824
#define SMEM_BYTES  (SMEM_FLOATS * 4)     // 151296 bytes

__device__ __forceinline__ uint64_t pk2(float lo, float hi) {
    uint64_t d; asm("mov.b64 %0, {%1, %2};" : "=l"(d) : "f"(lo), "f"(hi)); return d;
}
__device__ __forceinline__ void upk2(float& lo, float& hi, uint64_t v) {
    asm("mov.b64 {%0, %1}, %2;" : "=f"(lo), "=f"(hi) : "l"(v));
}
// Packed 2-wide fp32 FMA (FFMA2) — the 2x fp32 path ptxas won't emit from C++.
__device__ __forceinline__ uint64_t ffma2(uint64_t a, uint64_t b, uint64_t c) {
    uint64_t d; asm("fma.rn.f32x2 %0, %1, %2, %3;" : "=l"(d) : "l"(a), "l"(b), "l"(c)); return d;
}
__device__ __forceinline__ float ex2f(float v) {
    float y; asm("ex2.approx.f32 %0, %1;" : "=f"(y) : "f"(v)); return y;
}

__global__ __launch_bounds__(256, 1)
void aniso_fused_kernel(const float* __restrict__ x, const float* __restrict__ r,
                        const float* __restrict__ W1, const float* __restrict__ b1,
                        const float* __restrict__ W2, const float* __restrict__ b2,
                        float* __restrict__ out, int B)
{
    extern __shared__ float sm[];
    float* wbuf = sm + OFF_W;    // W1 then (reused) W2
    float* xsT  = sm + OFF_XS;   // x_sphere transposed [k][sample]
    float* hT   = sm + OFF_H;    // hidden transposed   [k][sample]
    float* escl = sm + OFF_ES;   // exp(nu * s) per sample

    const int tid  = threadIdx.x;
    const int lane = tid & 31;
    const int warp = tid >> 5;
    const long long gb = (long long)blockIdx.x * TILE_B;

    // ---- Load W1 -> smem [256][W1PAD] (coalesced gmem, conflict-free smem) ----
    #pragma unroll
    for (int m = 0; m < 64; ++m) {
        int idx = tid + m * 256;                       // 0..16383
        wbuf[(idx >> 6) * W1PAD + (idx & 63)] = W1[idx];
    }

    // ---- Phase A: per-sample Newton solve + x_sphere (warp per sample, 8 seq) ----
    const float r0 = r[lane], r1 = r[lane + 32];
    const float L2E = 1.4426950408889634f;
    const float q0 = -2.0f * r0 * L2E, q1 = -2.0f * r1 * L2E;
    const float d0 = -2.0f * r0,       d1 = -2.0f * r1;

    #pragma unroll 1
    for (int si = warp * 8; si < warp * 8 + 8; ++si) {
        long long row = gb + si; if (row >= B) row = B - 1;
        const float* xr = x + row * 64;
        float x0 = xr[lane], x1 = xr[lane + 32];
        float x20 = x0 * x0, x21 = x1 * x1;
        float s = 0.0f;
        unsigned nz = __ballot_sync(0xffffffffu,
                                    (fabsf(x0) > 1e-12f) || (fabsf(x1) > 1e-12f));
        if (nz) {
            #pragma unroll 1
            for (int it = 0; it < 30; ++it) {
                float t0 = ex2f(q0 * s) * x20;          // e^{-2 r s} x^2
                float t1 = ex2f(q1 * s) * x21;
                float val  = t0 + t1;
                float dval = d0 * t0 + d1 * t1;
                #pragma unroll
                for (int off = 16; off; off >>= 1) {
                    val  += __shfl_xor_sync(0xffffffffu, val,  off);
                    dval += __shfl_xor_sync(0xffffffffu, dval, off);
                }
                val -= 1.0f;                            // F(s)
                if (fabsf(val) < 1e-6f) break;          // frozen-step equivalence
                float sd = (dval == 0.0f) ? 1.0f : dval;
                s -= val / sd;
            }
        }
        xsT[lane * XSPAD + si]        = x0 * ex2f(-r0 * s * L2E);   // x * e^{-r s}
        xsT[(lane + 32) * XSPAD + si] = x1 * ex2f(-r1 * s * L2E);
        if (lane == 0) escl[si] = ex2f(s * L2E);        // e^{nu s}, nu = 1
    }
    __syncthreads();

    const int tx = tid & 7;          // sample block: s0 = tx*8 (4 packed pairs)
    const int ty = tid >> 3;         // 0..31
    const int s0 = tx * 8;

    // ---- GEMM1: h[64s][256h] = relu(Xs @ W1^T + b1), f32x2 over sample pairs ----
    {
        const int h0 = ty * 8;
        uint64_t acc[4][8];
        #pragma unroll
        for (int j = 0; j < 8; ++j) {
            float b = b1[h0 + j];
            uint64_t bb = pk2(b, b);
            #pragma unroll
            for (int i = 0; i < 4; ++i) acc[i][j] = bb;
        }
        #pragma unroll 4
        for (int k = 0; k < 64; ++k) {
            uint64_t a[4];
            #pragma unroll
            for (int i = 0; i < 4; ++i)
                a[i] = *(const uint64_t*)(xsT + k * XSPAD + s0 + 2 * i);
            #pragma unroll
            for (int j = 0; j < 8; ++j) {
                float w = wbuf[(h0 + j) * W1PAD + k];
                uint64_t wp = pk2(w, w);
                #pragma unroll
                for (int i = 0; i < 4; ++i) acc[i][j] = ffma2(a[i], wp, acc[i][j]);
            }
        }
        #pragma unroll
        for (int j = 0; j < 8; ++j) {
            #pragma unroll
            for (int i = 0; i < 4; ++i) {
                float lo, hi; upk2(lo, hi, acc[i][j]);
                *(float2*)(hT + (h0 + j) * HPAD + s0 + 2 * i) =
                    make_float2(fmaxf(lo, 0.0f), fmaxf(hi, 0.0f));
            }
        }
    }
    __syncthreads();

    // ---- Load W2 -> smem [64][W2PAD] (reuses W1 slot) ----
    #pragma unroll
    for (int m = 0; m < 64; ++m) {
        int idx = tid + m * 256;                       // 0..16383
        wbuf[(idx >> 8) * W2PAD + (idx & 255)] = W2[idx];
    }
    __syncthreads();

    // ---- GEMM2: out[64s][64o] = (H @ W2^T + b2) * exp(s) ----
    {
        const int o0 = ty * 2;
        uint64_t acc[4][2];
        #pragma unroll
        for (int j = 0; j < 2; ++j) {
            float b = b2[o0 + j];
            uint64_t bb = pk2(b, b);
            #pragma unroll
            for (int i = 0; i < 4; ++i) acc[i][j] = bb;
        }
        #pragma unroll 4
        for (int k = 0; k < 256; ++k) {
            uint64_t a[4];
            #pragma unroll
            for (int i = 0; i < 4; ++i)
                a[i] = *(const uint64_t*)(hT + k * HPAD + s0 + 2 * i);
            #pragma unroll
            for (int j = 0; j < 2; ++j) {
                float w = wbuf[(o0 + j) * W2PAD + k];
                uint64_t wp = pk2(w, w);
                #pragma unroll
                for (int i = 0; i < 4; ++i) acc[i][j] = ffma2(a[i], wp, acc[i][j]);
            }
        }
        #pragma unroll
        for (int i = 0; i < 4; ++i) {
            long long srow = gb + s0 + 2 * i;
            float e0 = escl[s0 + 2 * i];
            float e1 = escl[s0 + 2 * i + 1];
            float a0l, a0h, a1l, a1h;
            upk2(a0l, a0h, acc[i][0]);   // output o0   for samples (srow, srow+1)
            upk2(a1l, a1h, acc[i][1]);   // output o0+1 for samples (srow, srow+1)
            if (srow < B)
                *(float2*)(out + srow * 64 + o0)       = make_float2(a0l * e0, a1l * e0);
            if (srow + 1 < B)
                *(float2*)(out + (srow + 1) * 64 + o0) = make_float2(a0h * e1, a1h * e1);
        }
    }
}

extern "C" void kernel_launch(void* const* d_in, const int* in_sizes, int n_in,
                              void* d_out, int out_size) {
    const float* x  = (const float*)d_in[0];
    const float* r  = (const float*)d_in[1];
    const float* W1 = (const float*)d_in[2];
    const float* b1 = (const float*)d_in[3];
    const float* W2 = (const float*)d_in[4];
    const float* b2 = (const float*)d_in[5];
    float* out = (float*)d_out;

    const int B = in_sizes[0] / 64;
    const int grid = (B + TILE_B - 1) / TILE_B;

    cudaFuncSetAttribute(aniso_fused_kernel,
                         cudaFuncAttributeMaxDynamicSharedMemorySize, SMEM_BYTES);
    aniso_fused_kernel<<<grid, 256, SMEM_BYTES>>>(x, r, W1, b1, W2, b2, out, B);
}

// round 4
// speedup vs baseline: 4.1671x; 4.1671x over previous
#include <cuda_runtime.h>
#include <cuda_bf16.h>
#include <cstdint>

#define THREADS 512
#define TILE_B  128

// ---------------- smem byte map ----------------
#define OFF_XSH 0          // Xs hi  [128][64] bf16, swizzled   16384
#define OFF_XSL 16384      // Xs lo                              16384
#define OFF_WH  32768      // W hi: W1 [256][64] / W2 [64][256]  32768
#define OFF_WL  65536      // W lo                               32768
#define OFF_HH  98304      // H hi  [128][256] bf16              65536
#define OFF_HL  163840     // H lo                               65536
#define OFF_ES  229376     // escl 128 f32
#define OFF_B1  229888     // b1   256 f32
#define OFF_B2  230912     // b2    64 f32
#define SMEM_BYTES 231168

// Swizzled byte offset of 4B unit (row, p) in a tile with c2 = cols/2 units per row.
// XOR by 4*(row&7) keeps units within their 32-unit (128B) block -> conflict-free
// for all mma fragment access patterns used below.
#define U4(row, p, c2) ((((row) * (c2)) + ((p) ^ (((row) & 7) << 2))) << 2)

__device__ __forceinline__ float ex2f(float v) {
    float y; asm("ex2.approx.f32 %0, %1;" : "=f"(y) : "f"(v)); return y;
}
// pack two floats -> bf16x2 (lo -> low 16 bits)
__device__ __forceinline__ uint32_t packbf(float lo, float hi) {
    uint32_t d; asm("cvt.rn.satfinite.bf16x2.f32 %0, %1, %2;" : "=r"(d) : "f"(hi), "f"(lo)); return d;
}
__device__ __forceinline__ float bfhi(float v) {
    return __bfloat162float(__float2bfloat16(v));
}
__device__ __forceinline__ void mma16816(float* c, const uint32_t* a, uint32_t b0, uint32_t b1) {
    asm volatile(
        "mma.sync.aligned.m16n8k16.row.col.f32.bf16.bf16.f32 "
        "{%0,%1,%2,%3}, {%4,%5,%6,%7}, {%8,%9}, {%0,%1,%2,%3};"
        : "+f"(c[0]), "+f"(c[1]), "+f"(c[2]), "+f"(c[3])
        : "r"(a[0]), "r"(a[1]), "r"(a[2]), "r"(a[3]), "r"(b0), "r"(b1));
}

__global__ __launch_bounds__(THREADS, 1)
void aniso_mma_kernel(const float* __restrict__ x, const float* __restrict__ r,
                      const float* __restrict__ W1, const float* __restrict__ b1,
                      const float* __restrict__ W2, const float* __restrict__ b2,
                      float* __restrict__ out, int B)
{
    extern __shared__ char sm[];
    float* esclp = (float*)(sm + OFF_ES);
    float* b1s   = (float*)(sm + OFF_B1);
    float* b2s   = (float*)(sm + OFF_B2);

    const int tid  = threadIdx.x;
    const int lane = tid & 31;
    const int wid  = tid >> 5;
    const long long gb = (long long)blockIdx.x * TILE_B;

    // ---- biases ----
    if (tid < 256) b1s[tid] = b1[tid];
    if (tid < 64)  b2s[tid] = b2[tid];

    // ---- W1 fp32 -> bf16 hi/lo, swizzled [256 rows][32 units] ----
    #pragma unroll
    for (int i = 0; i < 16; ++i) {
        int p = tid + i * THREADS;             // pair 0..8191
        int row = p >> 5, up = p & 31;
        float2 w = *(const float2*)(W1 + (p << 1));
        float h0 = bfhi(w.x), h1 = bfhi(w.y);
        int off = U4(row, up, 32);
        *(uint32_t*)(sm + OFF_WH + off) = packbf(w.x, w.y);
        *(uint32_t*)(sm + OFF_WL + off) = packbf(w.x - h0, w.y - h1);
    }

    // ---- Newton: 4-lane group per sample, 16 elems per lane ----
    {
        const float L2E = 1.4426950408889634f;
        const int sg = lane >> 2;               // sample within warp 0..7
        const int cb = (lane & 3) << 4;         // col base 0/16/32/48
        const int m  = wid * 8 + sg;            // local sample 0..127
        long long row = gb + m; if (row >= B) row = B - 1;

        float X[16], X2[16], Q[16], R[16];
        #pragma unroll
        for (int q4 = 0; q4 < 4; ++q4) {
            float4 v = *(const float4*)(x + row * 64 + cb + q4 * 4);
            X[q4*4+0] = v.x; X[q4*4+1] = v.y; X[q4*4+2] = v.z; X[q4*4+3] = v.w;
            float4 rv = *(const float4*)(r + cb + q4 * 4);
            R[q4*4+0] = rv.x; R[q4*4+1] = rv.y; R[q4*4+2] = rv.z; R[q4*4+3] = rv.w;
        }
        #pragma unroll
        for (int j = 0; j < 16; ++j) { X2[j] = X[j] * X[j]; Q[j] = -2.0f * L2E * R[j]; }

        float s = 0.0f;
        bool conv = false;
        for (int it = 0; it < 30; ++it) {
            if (__all_sync(0xffffffffu, conv)) break;
            float val = 0.0f, dv = 0.0f;
            #pragma unroll
            for (int j = 0; j < 16; ++j) {
                float t = ex2f(Q[j] * s) * X2[j];
                val += t;
                dv  += R[j] * t;
            }
            val += __shfl_xor_sync(0xffffffffu, val, 1);
            dv  += __shfl_xor_sync(0xffffffffu, dv,  1);
            val += __shfl_xor_sync(0xffffffffu, val, 2);
            dv  += __shfl_xor_sync(0xffffffffu, dv,  2);
            if (it == 0 && val < 1e-20f) conv = true;     // all-zero sample -> s stays 0
            float F = val - 1.0f;
            if (fabsf(F) < 1e-6f) conv = true;            // frozen-step (reference semantics)
            float dval = -2.0f * dv;
            float denom = (dval == 0.0f) ? 1.0f : dval;
            if (!conv) s -= F / denom;
        }

        // x_sphere -> bf16 hi/lo (swizzled); pairs are lane-local (cols cb+j)
        #pragma unroll
        for (int j = 0; j < 16; j += 2) {
            float xs0 = X[j]     * ex2f(-R[j]     * L2E * s);
            float xs1 = X[j + 1] * ex2f(-R[j + 1] * L2E * s);
            float h0 = bfhi(xs0), h1 = bfhi(xs1);
            int p = (cb + j) >> 1;
            int off = U4(m, p, 32);
            *(uint32_t*)(sm + OFF_XSH + off) = packbf(xs0, xs1);
            *(uint32_t*)(sm + OFF_XSL + off) = packbf(xs0 - h0, xs1 - h1);
        }
        if ((lane & 3) == 0) esclp[m] = ex2f(L2E * s);    // e^{nu*s}, nu=1
    }
    __syncthreads();

    const int g  = lane >> 2;   // 0..7
    const int tg = lane & 3;    // 0..3
    const int mw = wid & 3;     // M tile: rows mw*32
    const int nw = wid >> 2;    // N tile

    // ---- GEMM1: [128 x 256] = Xs[128x64] @ W1^T, warp tile 32x64, 3 passes ----
    float acc[2][8][4];
    #pragma unroll
    for (int mi = 0; mi < 2; ++mi)
        #pragma unroll
        for (int j = 0; j < 8; ++j)
            #pragma unroll
            for (int q = 0; q < 4; ++q) acc[mi][j][q] = 0.0f;

    #pragma unroll
    for (int pass = 0; pass < 3; ++pass) {
        const char* As = sm + ((pass == 2) ? OFF_XSL : OFF_XSH);
        const char* Bs = sm + ((pass == 1) ? OFF_WL  : OFF_WH);
        #pragma unroll
        for (int kb2 = 0; kb2 < 32; kb2 += 8) {
            uint32_t a[2][4];
            #pragma unroll
            for (int mi = 0; mi < 2; ++mi) {
                int r0 = mw * 32 + mi * 16 + g;
                a[mi][0] = *(const uint32_t*)(As + U4(r0,     kb2 + tg,     32));
                a[mi][1] = *(const uint32_t*)(As + U4(r0 + 8, kb2 + tg,     32));
                a[mi][2] = *(const uint32_t*)(As + U4(r0,     kb2 + tg + 4, 32));
                a[mi][3] = *(const uint32_t*)(As + U4(r0 + 8, kb2 + tg + 4, 32));
            }
            #pragma unroll
            for (int j = 0; j < 8; ++j) {
                int n = nw * 64 + j * 8 + g;
                uint32_t b0 = *(const uint32_t*)(Bs + U4(n, kb2 + tg,     32));
                uint32_t b1v = *(const uint32_t*)(Bs + U4(n, kb2 + tg + 4, 32));
                mma16816(acc[0][j], a[0], b0, b1v);
                mma16816(acc[1][j], a[1], b0, b1v);
            }
        }
    }

    // ---- epilogue1: +b1, relu, split hi/lo -> H (swizzled) ----
    #pragma unroll
    for (int mi = 0; mi < 2; ++mi) {
        int r0 = mw * 32 + mi * 16 + g;
        #pragma unroll
        for (int j = 0; j < 8; ++j) {
            int col = nw * 64 + j * 8 + 2 * tg;
            int p = col >> 1;
            float bb0 = b1s[col], bb1 = b1s[col + 1];
            float v0 = fmaxf(acc[mi][j][0] + bb0, 0.0f);
            float v1 = fmaxf(acc[mi][j][1] + bb1, 0.0f);
            float v2 = fmaxf(acc[mi][j][2] + bb0, 0.0f);
            float v3 = fmaxf(acc[mi][j][3] + bb1, 0.0f);
            float h0 = bfhi(v0), h1 = bfhi(v1), h2 = bfhi(v2), h3 = bfhi(v3);
            int o0 = U4(r0,     p, 128);
            int o1 = U4(r0 + 8, p, 128);
            *(uint32_t*)(sm + OFF_HH + o0) = packbf(v0, v1);
            *(uint32_t*)(sm + OFF_HL + o0) = packbf(v0 - h0, v1 - h1);
            *(uint32_t*)(sm + OFF_HH + o1) = packbf(v2, v3);
            *(uint32_t*)(sm + OFF_HL + o1) = packbf(v2 - h2, v3 - h3);
        }
    }
    __syncthreads();

    // ---- W2 fp32 -> bf16 hi/lo into W slot [64 rows][128 units] ----
    #pragma unroll
    for (int i = 0; i < 16; ++i) {
        int p = tid + i * THREADS;             // pair 0..8191
        int row = p >> 7, up = p & 127;
        float2 w = *(const float2*)(W2 + (p << 1));
        float h0 = bfhi(w.x), h1 = bfhi(w.y);
        int off = U4(row, up, 128);
        *(uint32_t*)(sm + OFF_WH + off) = packbf(w.x, w.y);
        *(uint32_t*)(sm + OFF_WL + off) = packbf(w.x - h0, w.y - h1);
    }
    __syncthreads();

    // ---- GEMM2: [128 x 64] = H[128x256] @ W2^T, warp tile 32x16, 3 passes ----
    float acc2[2][2][4];
    #pragma unroll
    for (int mi = 0; mi < 2; ++mi)
        #pragma unroll
        for (int j = 0; j < 2; ++j)
            #pragma unroll
            for (int q = 0; q < 4; ++q) acc2[mi][j][q] = 0.0f;

    #pragma unroll
    for (int pass = 0; pass < 3; ++pass) {
        const char* As = sm + ((pass == 2) ? OFF_HL : OFF_HH);
        const char* Bs = sm + ((pass == 1) ? OFF_WL : OFF_WH);
        #pragma unroll 4
        for (int kb2 = 0; kb2 < 128; kb2 += 8) {
            uint32_t a[2][4];
            #pragma unroll
            for (int mi = 0; mi < 2; ++mi) {
                int r0 = mw * 32 + mi * 16 + g;
                a[mi][0] = *(const uint32_t*)(As + U4(r0,     kb2 + tg,     128));
                a[mi][1] = *(const uint32_t*)(As + U4(r0 + 8, kb2 + tg,     128));
                a[mi][2] = *(const uint32_t*)(As + U4(r0,     kb2 + tg + 4, 128));
                a[mi][3] = *(const uint32_t*)(As + U4(r0 + 8, kb2 + tg + 4, 128));
            }
            #pragma unroll
            for (int j = 0; j < 2; ++j) {
                int n = nw * 16 + j * 8 + g;
                uint32_t b0 = *(const uint32_t*)(Bs + U4(n, kb2 + tg,     128));
                uint32_t b1v = *(const uint32_t*)(Bs + U4(n, kb2 + tg + 4, 128));
                mma16816(acc2[0][j], a[0], b0, b1v);
                mma16816(acc2[1][j], a[1], b0, b1v);
            }
        }
    }

    // ---- epilogue2: +b2, * e^{s}, store ----
    #pragma unroll
    for (int mi = 0; mi < 2; ++mi) {
        int lr0 = mw * 32 + mi * 16 + g;
        int lr1 = lr0 + 8;
        float e0 = esclp[lr0], e1 = esclp[lr1];
        long long row0 = gb + lr0, row1 = gb + lr1;
        #pragma unroll
        for (int j = 0; j < 2; ++j) {
            int col = nw * 16 + j * 8 + 2 * tg;
            float bb0 = b2s[col], bb1 = b2s[col + 1];
            if (row0 < B)
                *(float2*)(out + row0 * 64 + col) =
                    make_float2((acc2[mi][j][0] + bb0) * e0, (acc2[mi][j][1] + bb1) * e0);
            if (row1 < B)
                *(float2*)(out + row1 * 64 + col) =
                    make_float2((acc2[mi][j][2] + bb0) * e1, (acc2[mi][j][3] + bb1) * e1);
        }
    }
}

extern "C" void kernel_launch(void* const* d_in, const int* in_sizes, int n_in,
                              void* d_out, int out_size) {
    const float* x  = (const float*)d_in[0];
    const float* r  = (const float*)d_in[1];
    const float* W1 = (const float*)d_in[2];
    const float* b1 = (const float*)d_in[3];
    const float* W2 = (const float*)d_in[4];
    const float* b2 = (const float*)d_in[5];
    float* out = (float*)d_out;

    const int B = in_sizes[0] / 64;
    const int grid = (B + TILE_B - 1) / TILE_B;

    cudaFuncSetAttribute(aniso_mma_kernel,
                         cudaFuncAttributeMaxDynamicSharedMemorySize, SMEM_BYTES);
    aniso_mma_kernel<<<grid, THREADS, SMEM_BYTES>>>(x, r, W1, b1, W2, b2, out, B);
}

// round 6
// speedup vs baseline: 4.8423x; 1.1620x over previous
#include <cuda_runtime.h>
#include <cuda_bf16.h>
#include <cstdint>

#define THREADS 512
#define TILE_B  128

// ---------------- smem byte map ----------------
#define OFF_XSH 0          // Xs hi  [128][64] bf16, swizzled   16384
#define OFF_XSL 16384      // Xs lo                              16384
#define OFF_WH  32768      // W hi: W1 [256][64] / W2 [64][256]  32768
#define OFF_WL  65536      // W lo                               32768
#define OFF_HH  98304      // H hi  [128][256] bf16              65536
#define OFF_HL  163840     // H lo                               65536
#define OFF_ES  229376     // escl 128 f32
#define OFF_B1  229888     // b1   256 f32
#define OFF_B2  230912     // b2    64 f32
#define SMEM_BYTES 231168

// Swizzled byte offset of 4B unit (row, p); c2 = units per row. XOR at 16B
// granularity (bits 2-4 of the unit index) -> 16B rows stay contiguous, so
// ldmatrix lane addresses are legal and all phases are bank-conflict-free.
#define U4(row, p, c2) ((((row) * (c2)) + ((p) ^ (((row) & 7) << 2))) << 2)

__device__ __forceinline__ float ex2f(float v) {
    float y; asm("ex2.approx.f32 %0, %1;" : "=f"(y) : "f"(v)); return y;
}
__device__ __forceinline__ float lg2f(float v) {
    float y; asm("lg2.approx.f32 %0, %1;" : "=f"(y) : "f"(v)); return y;
}
__device__ __forceinline__ uint32_t packbf(float lo, float hi) {
    uint32_t d; asm("cvt.rn.satfinite.bf16x2.f32 %0, %1, %2;" : "=r"(d) : "f"(hi), "f"(lo)); return d;
}
__device__ __forceinline__ float bfhi(float v) {
    return __bfloat162float(__float2bfloat16(v));
}
__device__ __forceinline__ void mma16816(float* c, const uint32_t* a, uint32_t b0, uint32_t b1) {
    asm volatile(
        "mma.sync.aligned.m16n8k16.row.col.f32.bf16.bf16.f32 "
        "{%0,%1,%2,%3}, {%4,%5,%6,%7}, {%8,%9}, {%0,%1,%2,%3};"
        : "+f"(c[0]), "+f"(c[1]), "+f"(c[2]), "+f"(c[3])
        : "r"(a[0]), "r"(a[1]), "r"(a[2]), "r"(a[3]), "r"(b0), "r"(b1));
}
__device__ __forceinline__ void ldm_x4(uint32_t* d, uint32_t addr) {
    asm volatile("ldmatrix.sync.aligned.m8n8.x4.shared.b16 {%0,%1,%2,%3}, [%4];"
        : "=r"(d[0]), "=r"(d[1]), "=r"(d[2]), "=r"(d[3]) : "r"(addr));
}

__global__ __launch_bounds__(THREADS, 1)
void aniso_mma_kernel(const float* __restrict__ x, const float* __restrict__ r,
                      const float* __restrict__ W1, const float* __restrict__ b1,
                      const float* __restrict__ W2, const float* __restrict__ b2,
                      float* __restrict__ out, int B)
{
    extern __shared__ char sm[];
    uint32_t smb;
    asm("{ .reg .u64 t; cvta.to.shared.u64 t, %1; cvt.u32.u64 %0, t; }" : "=r"(smb) : "l"(sm));
    float* esclp = (float*)(sm + OFF_ES);
    float* b1s   = (float*)(sm + OFF_B1);
    float* b2s   = (float*)(sm + OFF_B2);

    const int tid  = threadIdx.x;
    const int lane = tid & 31;
    const int wid  = tid >> 5;
    const long long gb = (long long)blockIdx.x * TILE_B;

    if (tid < 256) b1s[tid] = b1[tid];
    if (tid < 64)  b2s[tid] = b2[tid];

    // ---- W1 fp32 -> bf16 hi/lo, swizzled [256 rows][32 units] ----
    #pragma unroll
    for (int i = 0; i < 16; ++i) {
        int p = tid + i * THREADS;             // pair 0..8191
        int row = p >> 5, up = p & 31;
        float2 w = *(const float2*)(W1 + (p << 1));
        float h0 = bfhi(w.x), h1 = bfhi(w.y);
        int off = U4(row, up, 32);
        *(uint32_t*)(sm + OFF_WH + off) = packbf(w.x, w.y);
        *(uint32_t*)(sm + OFF_WL + off) = packbf(w.x - h0, w.y - h1);
    }

    // ---- Newton: 4-lane group per sample; warm start (provably <= root) ----
    {
        const float L2E = 1.4426950408889634f;
        const int sg = lane >> 2;
        const int cb = (lane & 3) << 4;
        const int m  = wid * 8 + sg;
        long long row = gb + m; if (row >= B) row = B - 1;

        float X[16], X2[16], Q[16], R[16];
        #pragma unroll
        for (int q4 = 0; q4 < 4; ++q4) {
            float4 v = *(const float4*)(x + row * 64 + cb + q4 * 4);
            X[q4*4+0] = v.x; X[q4*4+1] = v.y; X[q4*4+2] = v.z; X[q4*4+3] = v.w;
            float4 rv = *(const float4*)(r + cb + q4 * 4);
            R[q4*4+0] = rv.x; R[q4*4+1] = rv.y; R[q4*4+2] = rv.z; R[q4*4+3] = rv.w;
        }
        #pragma unroll
        for (int j = 0; j < 16; ++j) { X2[j] = X[j] * X[j]; Q[j] = -2.0f * L2E * R[j]; }

        // F, F' at s=0 — exp-free
        float val = 0.0f, dvr = 0.0f;
        #pragma unroll
        for (int j = 0; j < 16; ++j) { val += X2[j]; dvr += R[j] * X2[j]; }
        val += __shfl_xor_sync(0xffffffffu, val, 1);
        dvr += __shfl_xor_sync(0xffffffffu, dvr, 1);
        val += __shfl_xor_sync(0xffffffffu, val, 2);
        dvr += __shfl_xor_sync(0xffffffffu, dvr, 2);

        float s = 0.0f;
        bool conv = false;
        if (val < 1e-20f) conv = true;                     // all-zero sample
        else {
            float F0 = val - 1.0f;
            if (fabsf(F0) < 1e-6f) conv = true;
            else if (val > 1.0f)                           // Jensen: F(s_ws) >= 0
                s = val * lg2f(val) / ((2.0f * L2E) * dvr);
        }
        for (int it = 0; it < 30; ++it) {
            if (__all_sync(0xffffffffu, conv)) break;
            float v = 0.0f, d = 0.0f;
            #pragma unroll
            for (int j = 0; j < 16; ++j) {
                float t = ex2f(Q[j] * s) * X2[j];
                v += t; d += R[j] * t;
            }
            v += __shfl_xor_sync(0xffffffffu, v, 1);
            d += __shfl_xor_sync(0xffffffffu, d, 1);
            v += __shfl_xor_sync(0xffffffffu, v, 2);
            d += __shfl_xor_sync(0xffffffffu, d, 2);
            float F = v - 1.0f;
            if (fabsf(F) < 1e-6f) conv = true;
            float den = -2.0f * d;
            den = (den == 0.0f) ? 1.0f : den;
            if (!conv) s -= __fdividef(F, den);
        }

        #pragma unroll
        for (int j = 0; j < 16; j += 2) {
            float xs0 = X[j]     * ex2f(Q[j]     * 0.5f * s);   // x * e^{-r s}
            float xs1 = X[j + 1] * ex2f(Q[j + 1] * 0.5f * s);
            float h0 = bfhi(xs0), h1 = bfhi(xs1);
            int p = (cb + j) >> 1;
            int off = U4(m, p, 32);
            *(uint32_t*)(sm + OFF_XSH + off) = packbf(xs0, xs1);
            *(uint32_t*)(sm + OFF_XSL + off) = packbf(xs0 - h0, xs1 - h1);
        }
        if ((lane & 3) == 0) esclp[m] = ex2f(L2E * s);     // e^{nu*s}
    }
    __syncthreads();

    const int g  = lane >> 2;
    const int tg = lane & 3;
    const int mw = wid & 3;
    const int nw = wid >> 2;

    // ldmatrix lane addressing (row&7 invariant under +16 row steps -> xor fixed)
    const int lr  = lane & 7, seg = lane >> 3;
    const int arow = mw * 32 + lr + ((seg & 1) << 3);   // + mi*16
    const int apo  = (seg & 2) << 1;                    // 0 / 4 (k-high)
    const int axor = (arow & 7) << 2;
    const int brow1 = nw * 64 + lr + ((seg >> 1) << 3); // + jj*16 (GEMM1 B)
    const int bpo   = (seg & 1) << 2;
    const int bxor1 = (brow1 & 7) << 2;
    const int brow2 = nw * 16 + lr + ((seg >> 1) << 3); // GEMM2 B
    const int bxor2 = (brow2 & 7) << 2;

    // ---- GEMM1: [128x256] = Xs[128x64] @ W1^T, warp tile 32x64, 3 passes ----
    float acc[2][8][4];
    #pragma unroll
    for (int mi = 0; mi < 2; ++mi)
        #pragma unroll
        for (int j = 0; j < 8; ++j)
            #pragma unroll
            for (int q = 0; q < 4; ++q) acc[mi][j][q] = 0.0f;

    #pragma unroll
    for (int pass = 0; pass < 3; ++pass) {
        const uint32_t Ab = smb + ((pass == 2) ? OFF_XSL : OFF_XSH);
        const uint32_t Bb = smb + ((pass == 1) ? OFF_WL  : OFF_WH);
        const uint32_t aB = Ab + arow * 128;
        #pragma unroll
        for (int kb2 = 0; kb2 < 32; kb2 += 8) {
            uint32_t a[2][4];
            ldm_x4(a[0], aB +        (((kb2 + apo) ^ axor) << 2));
            ldm_x4(a[1], aB + 2048 + (((kb2 + apo) ^ axor) << 2));
            #pragma unroll
            for (int jj = 0; jj < 4; ++jj) {
                uint32_t q[4];
                ldm_x4(q, Bb + (brow1 + jj * 16) * 128 + (((kb2 + bpo) ^ bxor1) << 2));
                mma16816(acc[0][2*jj],     a[0], q[0], q[1]);
                mma16816(acc[1][2*jj],     a[1], q[0], q[1]);
                mma16816(acc[0][2*jj + 1], a[0], q[2], q[3]);
                mma16816(acc[1][2*jj + 1], a[1], q[2], q[3]);
            }
        }
    }

    // ---- epilogue1: +b1, relu, split hi/lo -> H (swizzled [128][128 units]) ----
    #pragma unroll
    for (int mi = 0; mi < 2; ++mi) {
        int r0 = mw * 32 + mi * 16 + g;
        #pragma unroll
        for (int j = 0; j < 8; ++j) {
            int col = nw * 64 + j * 8 + 2 * tg;
            int p = col >> 1;
            float bb0 = b1s[col], bb1 = b1s[col + 1];
            float v0 = fmaxf(acc[mi][j][0] + bb0, 0.0f);
            float v1 = fmaxf(acc[mi][j][1] + bb1, 0.0f);
            float v2 = fmaxf(acc[mi][j][2] + bb0, 0.0f);
            float v3 = fmaxf(acc[mi][j][3] + bb1, 0.0f);
            float h0 = bfhi(v0), h1 = bfhi(v1), h2 = bfhi(v2), h3 = bfhi(v3);
            int o0 = U4(r0,     p, 128);
            int o1 = U4(r0 + 8, p, 128);
            *(uint32_t*)(sm + OFF_HH + o0) = packbf(v0, v1);
            *(uint32_t*)(sm + OFF_HL + o0) = packbf(v0 - h0, v1 - h1);
            *(uint32_t*)(sm + OFF_HH + o1) = packbf(v2, v3);
            *(uint32_t*)(sm + OFF_HL + o1) = packbf(v2 - h2, v3 - h3);
        }
    }
    __syncthreads();

    // ---- W2 fp32 -> bf16 hi/lo [64 rows][128 units] ----
    #pragma unroll
    for (int i = 0; i < 16; ++i) {
        int p = tid + i * THREADS;
        int row = p >> 7, up = p & 127;
        float2 w = *(const float2*)(W2 + (p << 1));
        float h0 = bfhi(w.x), h1 = bfhi(w.y);
        int off = U4(row, up, 128);
        *(uint32_t*)(sm + OFF_WH + off) = packbf(w.x, w.y);
        *(uint32_t*)(sm + OFF_WL + off) = packbf(w.x - h0, w.y - h1);
    }
    __syncthreads();

    // ---- GEMM2: [128x64] = H[128x256] @ W2^T, warp tile 32x16, 3 passes ----
    float acc2[2][2][4];
    #pragma unroll
    for (int mi = 0; mi < 2; ++mi)
        #pragma unroll
        for (int j = 0; j < 2; ++j)
            #pragma unroll
            for (int q = 0; q < 4; ++q) acc2[mi][j][q] = 0.0f;

    #pragma unroll
    for (int pass = 0; pass < 3; ++pass) {
        const uint32_t Ab = smb + ((pass == 2) ? OFF_HL : OFF_HH);
        const uint32_t Bb = smb + ((pass == 1) ? OFF_WL : OFF_WH);
        const uint32_t aB = Ab + arow * 512;
        const uint32_t bB = Bb + brow2 * 512;
        #pragma unroll 8
        for (int kb2 = 0; kb2 < 128; kb2 += 8) {
            uint32_t a[2][4], q[4];
            ldm_x4(a[0], aB +        (((kb2 + apo) ^ axor) << 2));
            ldm_x4(a[1], aB + 8192 + (((kb2 + apo) ^ axor) << 2));
            ldm_x4(q,    bB +        (((kb2 + bpo) ^ bxor2) << 2));
            mma16816(acc2[0][0], a[0], q[0], q[1]);
            mma16816(acc2[1][0], a[1], q[0], q[1]);
            mma16816(acc2[0][1], a[0], q[2], q[3]);
            mma16816(acc2[1][1], a[1], q[2], q[3]);
        }
    }

    // ---- epilogue2: +b2, * e^{s}, store ----
    #pragma unroll
    for (int mi = 0; mi < 2; ++mi) {
        int lr0 = mw * 32 + mi * 16 + g;
        int lr1 = lr0 + 8;
        float e0 = esclp[lr0], e1 = esclp[lr1];
        long long row0 = gb + lr0, row1 = gb + lr1;
        #pragma unroll
        for (int j = 0; j < 2; ++j) {
            int col = nw * 16 + j * 8 + 2 * tg;
            float bb0 = b2s[col], bb1 = b2s[col + 1];
            if (row0 < B)
                *(float2*)(out + row0 * 64 + col) =
                    make_float2((acc2[mi][j][0] + bb0) * e0, (acc2[mi][j][1] + bb1) * e0);
            if (row1 < B)
                *(float2*)(out + row1 * 64 + col) =
                    make_float2((acc2[mi][j][2] + bb0) * e1, (acc2[mi][j][3] + bb1) * e1);
        }
    }
}

extern "C" void kernel_launch(void* const* d_in, const int* in_sizes, int n_in,
                              void* d_out, int out_size) {
    const float* x  = (const float*)d_in[0];
    const float* r  = (const float*)d_in[1];
    const float* W1 = (const float*)d_in[2];
    const float* b1 = (const float*)d_in[3];
    const float* W2 = (const float*)d_in[4];
    const float* b2 = (const float*)d_in[5];
    float* out = (float*)d_out;

    const int B = in_sizes[0] / 64;
    const int grid = (B + TILE_B - 1) / TILE_B;

    cudaFuncSetAttribute(aniso_mma_kernel,
                         cudaFuncAttributeMaxDynamicSharedMemorySize, SMEM_BYTES);
    aniso_mma_kernel<<<grid, THREADS, SMEM_BYTES>>>(x, r, W1, b1, W2, b2, out, B);
}

// round 8
// speedup vs baseline: 7.2626x; 1.4998x over previous
#include <cuda_runtime.h>
#include <cuda_fp16.h>
#include <cstdint>

#define THREADS 512
#define TILE_B  128

// ---------------- smem byte map ----------------
#define OFF_XSH 0          // Xs hi  [128][64] f16, swizzled    16384
#define OFF_W1H 16384      // W1 hi  [256][64]                  32768
#define OFF_W1L 49152      // W1 lo                             32768
#define OFF_W2H 81920      // W2 hi  [64][256]                  32768
#define OFF_W2L 114688     // W2 lo                             32768
#define OFF_HH  147456     // H hi   [128][256]                 65536
#define OFF_ES  212992     // escl 128 f32
#define OFF_B1  213504     // b1   256 f32
#define OFF_B2  214528     // b2    64 f32
#define SMEM_BYTES 215040

// Swizzled byte offset of 4B unit (row, p); c2 = units per row. XOR at 16B
// granularity -> ldmatrix-legal rows, conflict-free phases.
#define U4(row, p, c2) ((((row) * (c2)) + ((p) ^ (((row) & 7) << 2))) << 2)

// Pre-split, pre-swizzled weights: [W1H | W1L | W2H | W2L], 32KB each.
__device__ __align__(16) unsigned char g_Wbuf[131072];

__device__ __forceinline__ float ex2f(float v) {
    float y; asm("ex2.approx.f32 %0, %1;" : "=f"(y) : "f"(v)); return y;
}
__device__ __forceinline__ float lg2f(float v) {
    float y; asm("lg2.approx.f32 %0, %1;" : "=f"(y) : "f"(v)); return y;
}
__device__ __forceinline__ uint32_t packh(float lo, float hi) {
    half2 h = __floats2half2_rn(lo, hi);          // lo -> low half
    return *(uint32_t*)&h;
}
__device__ __forceinline__ void mma16816(float* c, const uint32_t* a, uint32_t b0, uint32_t b1) {
    asm volatile(
        "mma.sync.aligned.m16n8k16.row.col.f32.f16.f16.f32 "
        "{%0,%1,%2,%3}, {%4,%5,%6,%7}, {%8,%9}, {%0,%1,%2,%3};"
        : "+f"(c[0]), "+f"(c[1]), "+f"(c[2]), "+f"(c[3])
        : "r"(a[0]), "r"(a[1]), "r"(a[2]), "r"(a[3]), "r"(b0), "r"(b1));
}
__device__ __forceinline__ void ldm_x4(uint32_t* d, uint32_t addr) {
    asm volatile("ldmatrix.sync.aligned.m8n8.x4.shared.b16 {%0,%1,%2,%3}, [%4];"
        : "=r"(d[0]), "=r"(d[1]), "=r"(d[2]), "=r"(d[3]) : "r"(addr));
}

// ---------------- prep kernel: W fp32 -> fp16 hi/lo, swizzled ----------------
__global__ void prep_w_kernel(const float* __restrict__ W1, const float* __restrict__ W2) {
    int t = blockIdx.x * 256 + threadIdx.x;       // pair index 0..8191
    {
        float2 w = ((const float2*)W1)[t];
        half2 h = __floats2half2_rn(w.x, w.y);
        float l0 = w.x - __half2float(__low2half(h));
        float l1 = w.y - __half2float(__high2half(h));
        int off = U4(t >> 5, t & 31, 32);
        *(uint32_t*)(g_Wbuf + off)         = *(uint32_t*)&h;
        *(uint32_t*)(g_Wbuf + 32768 + off) = packh(l0, l1);
    }
    {
        float2 w = ((const float2*)W2)[t];
        half2 h = __floats2half2_rn(w.x, w.y);
        float l0 = w.x - __half2float(__low2half(h));
        float l1 = w.y - __half2float(__high2half(h));
        int off = U4(t >> 7, t & 127, 128);
        *(uint32_t*)(g_Wbuf + 65536 + off) = *(uint32_t*)&h;
        *(uint32_t*)(g_Wbuf + 98304 + off) = packh(l0, l1);
    }
}

__global__ __launch_bounds__(THREADS, 1)
void aniso_mma_kernel(const float* __restrict__ x, const float* __restrict__ r,
                      const float* __restrict__ b1, const float* __restrict__ b2,
                      float* __restrict__ out, int B)
{
    extern __shared__ char sm[];
    uint32_t smb;
    asm("{ .reg .u64 t; cvta.to.shared.u64 t, %1; cvt.u32.u64 %0, t; }" : "=r"(smb) : "l"(sm));
    float* esclp = (float*)(sm + OFF_ES);
    float* b1s   = (float*)(sm + OFF_B1);
    float* b2s   = (float*)(sm + OFF_B2);

    const int tid  = threadIdx.x;
    const int lane = tid & 31;
    const int wid  = tid >> 5;
    const long long gb = (long long)blockIdx.x * TILE_B;

    if (tid < 256) b1s[tid] = b1[tid];
    if (tid < 64)  b2s[tid] = b2[tid];

    // ---- bulk-copy pre-split weights (128KB) into smem ----
    #pragma unroll
    for (int i = 0; i < 16; ++i) {
        int u = tid + i * THREADS;                // 0..8191 uint4s
        *(uint4*)(sm + OFF_W1H + (u << 4)) = ((const uint4*)g_Wbuf)[u];
    }

    // ---- Newton: 4-lane group per sample; warm start (<= root) ----
    {
        const float L2E = 1.4426950408889634f;
        const int sg = lane >> 2;
        const int cb = (lane & 3) << 4;
        const int m  = wid * 8 + sg;
        long long row = gb + m; if (row >= B) row = B - 1;

        float X[16], X2[16], Q[16], R[16];
        #pragma unroll
        for (int q4 = 0; q4 < 4; ++q4) {
            float4 v = *(const float4*)(x + row * 64 + cb + q4 * 4);
            X[q4*4+0] = v.x; X[q4*4+1] = v.y; X[q4*4+2] = v.z; X[q4*4+3] = v.w;
            float4 rv = *(const float4*)(r + cb + q4 * 4);
            R[q4*4+0] = rv.x; R[q4*4+1] = rv.y; R[q4*4+2] = rv.z; R[q4*4+3] = rv.w;
        }
        #pragma unroll
        for (int j = 0; j < 16; ++j) { X2[j] = X[j] * X[j]; Q[j] = -2.0f * L2E * R[j]; }

        float val = 0.0f, dvr = 0.0f;
        #pragma unroll
        for (int j = 0; j < 16; ++j) { val += X2[j]; dvr += R[j] * X2[j]; }
        val += __shfl_xor_sync(0xffffffffu, val, 1);
        dvr += __shfl_xor_sync(0xffffffffu, dvr, 1);
        val += __shfl_xor_sync(0xffffffffu, val, 2);
        dvr += __shfl_xor_sync(0xffffffffu, dvr, 2);

        float s = 0.0f;
        bool conv = false;
        if (val < 1e-20f) conv = true;
        else {
            float F0 = val - 1.0f;
            if (fabsf(F0) < 1e-6f) conv = true;
            else if (val > 1.0f)
                s = val * lg2f(val) / ((2.0f * L2E) * dvr);
        }
        for (int it = 0; it < 30; ++it) {
            if (__all_sync(0xffffffffu, conv)) break;
            float v = 0.0f, d = 0.0f;
            #pragma unroll
            for (int j = 0; j < 16; ++j) {
                float t = ex2f(Q[j] * s) * X2[j];
                v += t; d += R[j] * t;
            }
            v += __shfl_xor_sync(0xffffffffu, v, 1);
            d += __shfl_xor_sync(0xffffffffu, d, 1);
            v += __shfl_xor_sync(0xffffffffu, v, 2);
            d += __shfl_xor_sync(0xffffffffu, d, 2);
            float F = v - 1.0f;
            if (fabsf(F) < 1e-6f) conv = true;
            float den = -2.0f * d;
            den = (den == 0.0f) ? 1.0f : den;
            if (!conv) s -= __fdividef(F, den);
        }

        #pragma unroll
        for (int j = 0; j < 16; j += 2) {
            float xs0 = X[j]     * ex2f(Q[j]     * 0.5f * s);   // x * e^{-r s}
            float xs1 = X[j + 1] * ex2f(Q[j + 1] * 0.5f * s);
            *(uint32_t*)(sm + OFF_XSH + U4(m, (cb + j) >> 1, 32)) = packh(xs0, xs1);
        }
        if ((lane & 3) == 0) esclp[m] = ex2f(L2E * s);
    }
    __syncthreads();

    const int g  = lane >> 2;
    const int tg = lane & 3;
    const int mw = wid & 3;
    const int nw = wid >> 2;

    const int lr  = lane & 7, seg = lane >> 3;
    const int arow = mw * 32 + lr + ((seg & 1) << 3);
    const int apo  = (seg & 2) << 1;
    const int axor = (arow & 7) << 2;
    const int brow1 = nw * 64 + lr + ((seg >> 1) << 3);
    const int bpo   = (seg & 1) << 2;
    const int bxor1 = (brow1 & 7) << 2;
    const int brow2 = nw * 16 + lr + ((seg >> 1) << 3);
    const int bxor2 = (brow2 & 7) << 2;

    // ---- GEMM1: [128x256] = Xh[128x64] @ (W1h+W1l)^T, warp tile 32x64 ----
    float acc[2][8][4];
    #pragma unroll
    for (int mi = 0; mi < 2; ++mi)
        #pragma unroll
        for (int j = 0; j < 8; ++j)
            #pragma unroll
            for (int q = 0; q < 4; ++q) acc[mi][j][q] = 0.0f;

    {
        const uint32_t aB = smb + OFF_XSH + arow * 128;
        #pragma unroll
        for (int kb2 = 0; kb2 < 32; kb2 += 8) {
            uint32_t a[2][4];
            ldm_x4(a[0], aB +        (((kb2 + apo) ^ axor) << 2));
            ldm_x4(a[1], aB + 2048 + (((kb2 + apo) ^ axor) << 2));
            #pragma unroll
            for (int jj = 0; jj < 4; ++jj) {
                uint32_t boff = (brow1 + jj * 16) * 128 + (((kb2 + bpo) ^ bxor1) << 2);
                uint32_t qh[4], ql[4];
                ldm_x4(qh, smb + OFF_W1H + boff);
                ldm_x4(ql, smb + OFF_W1L + boff);
                mma16816(acc[0][2*jj],     a[0], qh[0], qh[1]);
                mma16816(acc[1][2*jj],     a[1], qh[0], qh[1]);
                mma16816(acc[0][2*jj + 1], a[0], qh[2], qh[3]);
                mma16816(acc[1][2*jj + 1], a[1], qh[2], qh[3]);
                mma16816(acc[0][2*jj],     a[0], ql[0], ql[1]);
                mma16816(acc[1][2*jj],     a[1], ql[0], ql[1]);
                mma16816(acc[0][2*jj + 1], a[0], ql[2], ql[3]);
                mma16816(acc[1][2*jj + 1], a[1], ql[2], ql[3]);
            }
        }
    }

    // ---- epilogue1: +b1, relu -> H hi (swizzled [128][128 units]) ----
    #pragma unroll
    for (int mi = 0; mi < 2; ++mi) {
        int r0 = mw * 32 + mi * 16 + g;
        #pragma unroll
        for (int j = 0; j < 8; ++j) {
            int col = nw * 64 + j * 8 + 2 * tg;
            int p = col >> 1;
            float bb0 = b1s[col], bb1 = b1s[col + 1];
            float v0 = fmaxf(acc[mi][j][0] + bb0, 0.0f);
            float v1 = fmaxf(acc[mi][j][1] + bb1, 0.0f);
            float v2 = fmaxf(acc[mi][j][2] + bb0, 0.0f);
            float v3 = fmaxf(acc[mi][j][3] + bb1, 0.0f);
            *(uint32_t*)(sm + OFF_HH + U4(r0,     p, 128)) = packh(v0, v1);
            *(uint32_t*)(sm + OFF_HH + U4(r0 + 8, p, 128)) = packh(v2, v3);
        }
    }
    __syncthreads();

    // ---- GEMM2: [128x64] = Hh[128x256] @ (W2h+W2l)^T, warp tile 32x16 ----
    float acc2[2][2][4];
    #pragma unroll
    for (int mi = 0; mi < 2; ++mi)
        #pragma unroll
        for (int j = 0; j < 2; ++j)
            #pragma unroll
            for (int q = 0; q < 4; ++q) acc2[mi][j][q] = 0.0f;

    {
        const uint32_t aB = smb + OFF_HH + arow * 512;
        const uint32_t bo2 = brow2 * 512;
        #pragma unroll 4
        for (int kb2 = 0; kb2 < 128; kb2 += 8) {
            uint32_t a[2][4], qh[4], ql[4];
            ldm_x4(a[0], aB +        (((kb2 + apo) ^ axor) << 2));
            ldm_x4(a[1], aB + 8192 + (((kb2 + apo) ^ axor) << 2));
            uint32_t boff = bo2 + (((kb2 + bpo) ^ bxor2) << 2);
            ldm_x4(qh, smb + OFF_W2H + boff);
            ldm_x4(ql, smb + OFF_W2L + boff);
            mma16816(acc2[0][0], a[0], qh[0], qh[1]);
            mma16816(acc2[1][0], a[1], qh[0], qh[1]);
            mma16816(acc2[0][1], a[0], qh[2], qh[3]);
            mma16816(acc2[1][1], a[1], qh[2], qh[3]);
            mma16816(acc2[0][0], a[0], ql[0], ql[1]);
            mma16816(acc2[1][0], a[1], ql[0], ql[1]);
            mma16816(acc2[0][1], a[0], ql[2], ql[3]);
            mma16816(acc2[1][1], a[1], ql[2], ql[3]);
        }
    }

    // ---- epilogue2: +b2, * e^{s}, store ----
    #pragma unroll
    for (int mi = 0; mi < 2; ++mi) {
        int lr0 = mw * 32 + mi * 16 + g;
        int lr1 = lr0 + 8;
        float e0 = esclp[lr0], e1 = esclp[lr1];
        long long row0 = gb + lr0, row1 = gb + lr1;
        #pragma unroll
        for (int j = 0; j < 2; ++j) {
            int col = nw * 16 + j * 8 + 2 * tg;
            float bb0 = b2s[col], bb1 = b2s[col + 1];
            if (row0 < B)
                *(float2*)(out + row0 * 64 + col) =
                    make_float2((acc2[mi][j][0] + bb0) * e0, (acc2[mi][j][1] + bb1) * e0);
            if (row1 < B)
                *(float2*)(out + row1 * 64 + col) =
                    make_float2((acc2[mi][j][2] + bb0) * e1, (acc2[mi][j][3] + bb1) * e1);
        }
    }
}

extern "C" void kernel_launch(void* const* d_in, const int* in_sizes, int n_in,
                              void* d_out, int out_size) {
    const float* x  = (const float*)d_in[0];
    const float* r  = (const float*)d_in[1];
    const float* W1 = (const float*)d_in[2];
    const float* b1 = (const float*)d_in[3];
    const float* W2 = (const float*)d_in[4];
    const float* b2 = (const float*)d_in[5];
    float* out = (float*)d_out;

    const int B = in_sizes[0] / 64;
    const int grid = (B + TILE_B - 1) / TILE_B;

    prep_w_kernel<<<32, 256>>>(W1, W2);

    cudaFuncSetAttribute(aniso_mma_kernel,
                         cudaFuncAttributeMaxDynamicSharedMemorySize, SMEM_BYTES);
    aniso_mma_kernel<<<grid, THREADS, SMEM_BYTES>>>(x, r, b1, b2, out, B);
}

// round 9
// speedup vs baseline: 7.5372x; 1.0378x over previous
#include <cuda_runtime.h>
#include <cuda_fp16.h>
#include <cstdint>

#define THREADS 256
#define TILE_B  64

// ---------------- smem byte map (per CTA, 2 CTAs/SM) ----------------
#define OFF_XS  0          // Xs hi [64][64] f16, swizzled        8192
#define OFF_W   8192       // W slot: W1h|W1l then W2h|W2l       65536
#define OFF_H   73728      // H hi  [64][256] f16                32768
#define OFF_ES  106496     // escl 64 f32
#define OFF_B1  106752     // b1  256 f32
#define OFF_B2  107776     // b2   64 f32
#define SMEM_BYTES 108032

// Swizzled byte offset of 4B unit (row, p); c2 = units per row. XOR at 16B
// granularity -> ldmatrix-legal rows, conflict-free phases.
#define U4(row, p, c2) ((((row) * (c2)) + ((p) ^ (((row) & 7) << 2))) << 2)

// Pre-split, pre-swizzled weights: [W1H | W1L | W2H | W2L], 32KB each.
__device__ __align__(16) unsigned char g_Wbuf[131072];

__device__ __forceinline__ float ex2f(float v) {
    float y; asm("ex2.approx.f32 %0, %1;" : "=f"(y) : "f"(v)); return y;
}
__device__ __forceinline__ float lg2f(float v) {
    float y; asm("lg2.approx.f32 %0, %1;" : "=f"(y) : "f"(v)); return y;
}
__device__ __forceinline__ uint32_t packh(float lo, float hi) {
    half2 h = __floats2half2_rn(lo, hi);          // lo -> low half
    return *(uint32_t*)&h;
}
__device__ __forceinline__ void mma16816(float* c, const uint32_t* a, uint32_t b0, uint32_t b1) {
    asm volatile(
        "mma.sync.aligned.m16n8k16.row.col.f32.f16.f16.f32 "
        "{%0,%1,%2,%3}, {%4,%5,%6,%7}, {%8,%9}, {%0,%1,%2,%3};"
        : "+f"(c[0]), "+f"(c[1]), "+f"(c[2]), "+f"(c[3])
        : "r"(a[0]), "r"(a[1]), "r"(a[2]), "r"(a[3]), "r"(b0), "r"(b1));
}
__device__ __forceinline__ void ldm_x4(uint32_t* d, uint32_t addr) {
    asm volatile("ldmatrix.sync.aligned.m8n8.x4.shared.b16 {%0,%1,%2,%3}, [%4];"
        : "=r"(d[0]), "=r"(d[1]), "=r"(d[2]), "=r"(d[3]) : "r"(addr));
}

// ---------------- prep kernel: W fp32 -> fp16 hi/lo, swizzled ----------------
__global__ void prep_w_kernel(const float* __restrict__ W1, const float* __restrict__ W2) {
    int t = blockIdx.x * 256 + threadIdx.x;       // pair index 0..8191
    {
        float2 w = ((const float2*)W1)[t];
        half2 h = __floats2half2_rn(w.x, w.y);
        float l0 = w.x - __half2float(__low2half(h));
        float l1 = w.y - __half2float(__high2half(h));
        int off = U4(t >> 5, t & 31, 32);
        *(uint32_t*)(g_Wbuf + off)         = *(uint32_t*)&h;
        *(uint32_t*)(g_Wbuf + 32768 + off) = packh(l0, l1);
    }
    {
        float2 w = ((const float2*)W2)[t];
        half2 h = __floats2half2_rn(w.x, w.y);
        float l0 = w.x - __half2float(__low2half(h));
        float l1 = w.y - __half2float(__high2half(h));
        int off = U4(t >> 7, t & 127, 128);
        *(uint32_t*)(g_Wbuf + 65536 + off) = *(uint32_t*)&h;
        *(uint32_t*)(g_Wbuf + 98304 + off) = packh(l0, l1);
    }
}

__global__ __launch_bounds__(THREADS, 2)
void aniso_mma_kernel(const float* __restrict__ x, const float* __restrict__ r,
                      const float* __restrict__ b1, const float* __restrict__ b2,
                      float* __restrict__ out, int B)
{
    extern __shared__ char sm[];
    uint32_t smb;
    asm("{ .reg .u64 t; cvta.to.shared.u64 t, %1; cvt.u32.u64 %0, t; }" : "=r"(smb) : "l"(sm));
    float* esclp = (float*)(sm + OFF_ES);
    float* b1s   = (float*)(sm + OFF_B1);
    float* b2s   = (float*)(sm + OFF_B2);

    const int tid  = threadIdx.x;
    const int lane = tid & 31;
    const int wid  = tid >> 5;
    const long long gb = (long long)blockIdx.x * TILE_B;

    b1s[tid] = b1[tid & 255];
    if (tid < 64) b2s[tid] = b2[tid];

    // ---- copy W1 (hi|lo, 64KB) into smem ----
    #pragma unroll
    for (int i = 0; i < 16; ++i) {
        int u = tid + i * THREADS;                // 0..4095 uint4s
        *(uint4*)(sm + OFF_W + (u << 4)) = ((const uint4*)g_Wbuf)[u];
    }

    // ---- Newton: 4-lane group per sample; warm start (<= root) ----
    {
        const float L2E = 1.4426950408889634f;
        const int sg = lane >> 2;
        const int cb = (lane & 3) << 4;
        const int m  = wid * 8 + sg;              // 0..63
        long long row = gb + m; if (row >= B) row = B - 1;

        float X[16], X2[16], Q[16], R[16];
        #pragma unroll
        for (int q4 = 0; q4 < 4; ++q4) {
            float4 v = *(const float4*)(x + row * 64 + cb + q4 * 4);
            X[q4*4+0] = v.x; X[q4*4+1] = v.y; X[q4*4+2] = v.z; X[q4*4+3] = v.w;
            float4 rv = *(const float4*)(r + cb + q4 * 4);
            R[q4*4+0] = rv.x; R[q4*4+1] = rv.y; R[q4*4+2] = rv.z; R[q4*4+3] = rv.w;
        }
        #pragma unroll
        for (int j = 0; j < 16; ++j) { X2[j] = X[j] * X[j]; Q[j] = -2.0f * L2E * R[j]; }

        float val = 0.0f, dvr = 0.0f;
        #pragma unroll
        for (int j = 0; j < 16; ++j) { val += X2[j]; dvr += R[j] * X2[j]; }
        val += __shfl_xor_sync(0xffffffffu, val, 1);
        dvr += __shfl_xor_sync(0xffffffffu, dvr, 1);
        val += __shfl_xor_sync(0xffffffffu, val, 2);
        dvr += __shfl_xor_sync(0xffffffffu, dvr, 2);

        float s = 0.0f;
        bool conv = false;
        if (val < 1e-20f) conv = true;
        else {
            float F0 = val - 1.0f;
            if (fabsf(F0) < 1e-6f) conv = true;
            else if (val > 1.0f)
                s = val * lg2f(val) / ((2.0f * L2E) * dvr);   // Jensen: F(s_ws) >= 0
        }
        for (int it = 0; it < 30; ++it) {
            if (__all_sync(0xffffffffu, conv)) break;
            float v = 0.0f, d = 0.0f;
            #pragma unroll
            for (int j = 0; j < 16; ++j) {
                float t = ex2f(Q[j] * s) * X2[j];
                v += t; d += R[j] * t;
            }
            v += __shfl_xor_sync(0xffffffffu, v, 1);
            d += __shfl_xor_sync(0xffffffffu, d, 1);
            v += __shfl_xor_sync(0xffffffffu, v, 2);
            d += __shfl_xor_sync(0xffffffffu, d, 2);
            float F = v - 1.0f;
            if (fabsf(F) < 1e-6f) conv = true;
            float den = -2.0f * d;
            den = (den == 0.0f) ? 1.0f : den;
            if (!conv) s -= __fdividef(F, den);
        }

        #pragma unroll
        for (int j = 0; j < 16; j += 2) {
            float xs0 = X[j]     * ex2f(Q[j]     * 0.5f * s);   // x * e^{-r s}
            float xs1 = X[j + 1] * ex2f(Q[j + 1] * 0.5f * s);
            *(uint32_t*)(sm + OFF_XS + U4(m, (cb + j) >> 1, 32)) = packh(xs0, xs1);
        }
        if ((lane & 3) == 0) esclp[m] = ex2f(L2E * s);
    }
    __syncthreads();

    const int g  = lane >> 2;
    const int tg = lane & 3;
    const int mw = wid & 1;      // 2 M tiles of 32
    const int nw = wid >> 1;     // 4 N tiles

    const int lr  = lane & 7, seg = lane >> 3;
    const int arow = mw * 32 + lr + ((seg & 1) << 3);
    const int apo  = (seg & 2) << 1;
    const int axor = (arow & 7) << 2;
    const int brow1 = nw * 64 + lr + ((seg >> 1) << 3);   // W1 rows 0..255
    const int bpo   = (seg & 1) << 2;
    const int bxor1 = (brow1 & 7) << 2;
    const int brow2 = nw * 16 + lr + ((seg >> 1) << 3);   // W2 rows 0..63
    const int bxor2 = (brow2 & 7) << 2;

    // ---- GEMM1: [64x256] = Xh[64x64] @ (W1h+W1l)^T, warp tile 32x64 ----
    float acc[2][8][4];
    #pragma unroll
    for (int mi = 0; mi < 2; ++mi)
        #pragma unroll
        for (int j = 0; j < 8; ++j)
            #pragma unroll
            for (int q = 0; q < 4; ++q) acc[mi][j][q] = 0.0f;

    {
        const uint32_t aB = smb + OFF_XS + arow * 128;
        #pragma unroll
        for (int kb2 = 0; kb2 < 32; kb2 += 8) {
            uint32_t a[2][4];
            ldm_x4(a[0], aB +        (((kb2 + apo) ^ axor) << 2));
            ldm_x4(a[1], aB + 2048 + (((kb2 + apo) ^ axor) << 2));
            #pragma unroll
            for (int jj = 0; jj < 4; ++jj) {
                uint32_t boff = (brow1 + jj * 16) * 128 + (((kb2 + bpo) ^ bxor1) << 2);
                uint32_t qh[4], ql[4];
                ldm_x4(qh, smb + OFF_W + boff);
                ldm_x4(ql, smb + OFF_W + 32768 + boff);
                mma16816(acc[0][2*jj],     a[0], qh[0], qh[1]);
                mma16816(acc[1][2*jj],     a[1], qh[0], qh[1]);
                mma16816(acc[0][2*jj + 1], a[0], qh[2], qh[3]);
                mma16816(acc[1][2*jj + 1], a[1], qh[2], qh[3]);
                mma16816(acc[0][2*jj],     a[0], ql[0], ql[1]);
                mma16816(acc[1][2*jj],     a[1], ql[0], ql[1]);
                mma16816(acc[0][2*jj + 1], a[0], ql[2], ql[3]);
                mma16816(acc[1][2*jj + 1], a[1], ql[2], ql[3]);
            }
        }
    }

    // ---- epilogue1: +b1, relu -> H hi (swizzled [64][128 units]) ----
    #pragma unroll
    for (int mi = 0; mi < 2; ++mi) {
        int r0 = mw * 32 + mi * 16 + g;
        #pragma unroll
        for (int j = 0; j < 8; ++j) {
            int col = nw * 64 + j * 8 + 2 * tg;
            int p = col >> 1;
            float bb0 = b1s[col], bb1 = b1s[col + 1];
            float v0 = fmaxf(acc[mi][j][0] + bb0, 0.0f);
            float v1 = fmaxf(acc[mi][j][1] + bb1, 0.0f);
            float v2 = fmaxf(acc[mi][j][2] + bb0, 0.0f);
            float v3 = fmaxf(acc[mi][j][3] + bb1, 0.0f);
            *(uint32_t*)(sm + OFF_H + U4(r0,     p, 128)) = packh(v0, v1);
            *(uint32_t*)(sm + OFF_H + U4(r0 + 8, p, 128)) = packh(v2, v3);
        }
    }
    __syncthreads();

    // ---- reload W2 (hi|lo, 64KB) into the W slot ----
    #pragma unroll
    for (int i = 0; i < 16; ++i) {
        int u = tid + i * THREADS;
        *(uint4*)(sm + OFF_W + (u << 4)) = ((const uint4*)(g_Wbuf + 65536))[u];
    }
    __syncthreads();

    // ---- GEMM2: [64x64] = Hh[64x256] @ (W2h+W2l)^T, warp tile 32x16 ----
    float acc2[2][2][4];
    #pragma unroll
    for (int mi = 0; mi < 2; ++mi)
        #pragma unroll
        for (int j = 0; j < 2; ++j)
            #pragma unroll
            for (int q = 0; q < 4; ++q) acc2[mi][j][q] = 0.0f;

    {
        const uint32_t aB = smb + OFF_H + arow * 512;
        const uint32_t bo2 = brow2 * 512;
        #pragma unroll 4
        for (int kb2 = 0; kb2 < 128; kb2 += 8) {
            uint32_t a[2][4], qh[4], ql[4];
            ldm_x4(a[0], aB +        (((kb2 + apo) ^ axor) << 2));
            ldm_x4(a[1], aB + 8192 + (((kb2 + apo) ^ axor) << 2));
            uint32_t boff = bo2 + (((kb2 + bpo) ^ bxor2) << 2);
            ldm_x4(qh, smb + OFF_W + boff);
            ldm_x4(ql, smb + OFF_W + 32768 + boff);
            mma16816(acc2[0][0], a[0], qh[0], qh[1]);
            mma16816(acc2[1][0], a[1], qh[0], qh[1]);
            mma16816(acc2[0][1], a[0], qh[2], qh[3]);
            mma16816(acc2[1][1], a[1], qh[2], qh[3]);
            mma16816(acc2[0][0], a[0], ql[0], ql[1]);
            mma16816(acc2[1][0], a[1], ql[0], ql[1]);
            mma16816(acc2[0][1], a[0], ql[2], ql[3]);
            mma16816(acc2[1][1], a[1], ql[2], ql[3]);
        }
    }

    // ---- epilogue2: +b2, * e^{s}, store ----
    #pragma unroll
    for (int mi = 0; mi < 2; ++mi) {
        int lr0 = mw * 32 + mi * 16 + g;
        int lr1 = lr0 + 8;
        float e0 = esclp[lr0], e1 = esclp[lr1];
        long long row0 = gb + lr0, row1 = gb + lr1;
        #pragma unroll
        for (int j = 0; j < 2; ++j) {
            int col = nw * 16 + j * 8 + 2 * tg;
            float bb0 = b2s[col], bb1 = b2s[col + 1];
            if (row0 < B)
                *(float2*)(out + row0 * 64 + col) =
                    make_float2((acc2[mi][j][0] + bb0) * e0, (acc2[mi][j][1] + bb1) * e0);
            if (row1 < B)
                *(float2*)(out + row1 * 64 + col) =
                    make_float2((acc2[mi][j][2] + bb0) * e1, (acc2[mi][j][3] + bb1) * e1);
        }
    }
}

extern "C" void kernel_launch(void* const* d_in, const int* in_sizes, int n_in,
                              void* d_out, int out_size) {
    const float* x  = (const float*)d_in[0];
    const float* r  = (const float*)d_in[1];
    const float* W1 = (const float*)d_in[2];
    const float* b1 = (const float*)d_in[3];
    const float* W2 = (const float*)d_in[4];
    const float* b2 = (const float*)d_in[5];
    float* out = (float*)d_out;

    const int B = in_sizes[0] / 64;
    const int grid = (B + TILE_B - 1) / TILE_B;

    prep_w_kernel<<<32, 256>>>(W1, W2);

    cudaFuncSetAttribute(aniso_mma_kernel,
                         cudaFuncAttributeMaxDynamicSharedMemorySize, SMEM_BYTES);
    aniso_mma_kernel<<<grid, THREADS, SMEM_BYTES>>>(x, r, b1, b2, out, B);
}

// round 10
// speedup vs baseline: 8.7359x; 1.1590x over previous
#include <cuda_runtime.h>
#include <cuda_fp16.h>
#include <cstdint>

#define THREADS 256
#define TILE_B  64

// ---------------- smem byte map (per CTA, 2 CTAs/SM) ----------------
// H (32KB) aliases W1H after GEMM1 completes (sync-separated).
#define OFF_XS  0          // Xs hi [64][64] f16, swizzled        8192
#define OFF_W1H 8192       // W1 hi [256][64]                    32768
#define OFF_W1L 40960      // W1 lo                              32768
#define OFF_W2H 73728      // W2 hi [64][256]                    32768
#define OFF_H   8192       // H hi  [64][256]  (aliases W1H)     32768
#define OFF_ES  106496     // escl 64 f32
#define OFF_B1  106752     // b1  256 f32
#define OFF_B2  107776     // b2   64 f32
#define SMEM_BYTES 108032

// Swizzled byte offset of 4B unit (row, p); c2 = units per row. XOR at 16B
// granularity -> ldmatrix-legal rows, conflict-free phases.
#define U4(row, p, c2) ((((row) * (c2)) + ((p) ^ (((row) & 7) << 2))) << 2)

// Pre-split, pre-swizzled weights: [W1H | W1L | W2H], 32KB each.
__device__ __align__(16) unsigned char g_Wbuf[98304];

__device__ __forceinline__ float ex2f(float v) {
    float y; asm("ex2.approx.f32 %0, %1;" : "=f"(y) : "f"(v)); return y;
}
__device__ __forceinline__ float lg2f(float v) {
    float y; asm("lg2.approx.f32 %0, %1;" : "=f"(y) : "f"(v)); return y;
}
__device__ __forceinline__ uint32_t packh(float lo, float hi) {
    half2 h = __floats2half2_rn(lo, hi);          // lo -> low half
    return *(uint32_t*)&h;
}
__device__ __forceinline__ void mma16816(float* c, const uint32_t* a, uint32_t b0, uint32_t b1) {
    asm volatile(
        "mma.sync.aligned.m16n8k16.row.col.f32.f16.f16.f32 "
        "{%0,%1,%2,%3}, {%4,%5,%6,%7}, {%8,%9}, {%0,%1,%2,%3};"
        : "+f"(c[0]), "+f"(c[1]), "+f"(c[2]), "+f"(c[3])
        : "r"(a[0]), "r"(a[1]), "r"(a[2]), "r"(a[3]), "r"(b0), "r"(b1));
}
__device__ __forceinline__ void ldm_x4(uint32_t* d, uint32_t addr) {
    asm volatile("ldmatrix.sync.aligned.m8n8.x4.shared.b16 {%0,%1,%2,%3}, [%4];"
        : "=r"(d[0]), "=r"(d[1]), "=r"(d[2]), "=r"(d[3]) : "r"(addr));
}
__device__ __forceinline__ void cp4(uint32_t* d, const uint32_t* s) {
    d[0] = s[0]; d[1] = s[1]; d[2] = s[2]; d[3] = s[3];
}

// ---------------- prep kernel: W fp32 -> fp16 (W1 hi/lo, W2 hi), swizzled ----
__global__ void prep_w_kernel(const float* __restrict__ W1, const float* __restrict__ W2) {
    int t = blockIdx.x * 256 + threadIdx.x;       // pair index 0..8191
    {
        float2 w = ((const float2*)W1)[t];
        half2 h = __floats2half2_rn(w.x, w.y);
        float l0 = w.x - __half2float(__low2half(h));
        float l1 = w.y - __half2float(__high2half(h));
        int off = U4(t >> 5, t & 31, 32);
        *(uint32_t*)(g_Wbuf + off)         = *(uint32_t*)&h;
        *(uint32_t*)(g_Wbuf + 32768 + off) = packh(l0, l1);
    }
    {
        float2 w = ((const float2*)W2)[t];
        half2 h = __floats2half2_rn(w.x, w.y);
        int off = U4(t >> 7, t & 127, 128);
        *(uint32_t*)(g_Wbuf + 65536 + off) = *(uint32_t*)&h;
    }
}

__global__ __launch_bounds__(THREADS, 2)
void aniso_mma_kernel(const float* __restrict__ x, const float* __restrict__ r,
                      const float* __restrict__ b1, const float* __restrict__ b2,
                      float* __restrict__ out, int B)
{
    extern __shared__ char sm[];
    uint32_t smb;
    asm("{ .reg .u64 t; cvta.to.shared.u64 t, %1; cvt.u32.u64 %0, t; }" : "=r"(smb) : "l"(sm));
    float* esclp = (float*)(sm + OFF_ES);
    float* b1s   = (float*)(sm + OFF_B1);
    float* b2s   = (float*)(sm + OFF_B2);

    const int tid  = threadIdx.x;
    const int lane = tid & 31;
    const int wid  = tid >> 5;
    const long long gb = (long long)blockIdx.x * TILE_B;

    b1s[tid] = b1[tid & 255];
    if (tid < 64) b2s[tid] = b2[tid];

    // ---- copy W1h|W1l|W2h (96KB) into smem ----
    #pragma unroll
    for (int i = 0; i < 24; ++i) {
        int u = tid + i * THREADS;                // 0..6143 uint4s
        *(uint4*)(sm + OFF_W1H + (u << 4)) = ((const uint4*)g_Wbuf)[u];
    }

    // ---- Newton: 4-lane group per sample; warm start (<= root) ----
    {
        const float L2E = 1.4426950408889634f;
        const int sg = lane >> 2;
        const int cb = (lane & 3) << 4;
        const int m  = wid * 8 + sg;              // 0..63
        long long row = gb + m; if (row >= B) row = B - 1;

        float X[16], X2[16], Q[16], R[16];
        #pragma unroll
        for (int q4 = 0; q4 < 4; ++q4) {
            float4 v = *(const float4*)(x + row * 64 + cb + q4 * 4);
            X[q4*4+0] = v.x; X[q4*4+1] = v.y; X[q4*4+2] = v.z; X[q4*4+3] = v.w;
            float4 rv = *(const float4*)(r + cb + q4 * 4);
            R[q4*4+0] = rv.x; R[q4*4+1] = rv.y; R[q4*4+2] = rv.z; R[q4*4+3] = rv.w;
        }
        #pragma unroll
        for (int j = 0; j < 16; ++j) { X2[j] = X[j] * X[j]; Q[j] = -2.0f * L2E * R[j]; }

        float val = 0.0f, dvr = 0.0f;
        #pragma unroll
        for (int j = 0; j < 16; ++j) { val += X2[j]; dvr += R[j] * X2[j]; }
        val += __shfl_xor_sync(0xffffffffu, val, 1);
        dvr += __shfl_xor_sync(0xffffffffu, dvr, 1);
        val += __shfl_xor_sync(0xffffffffu, val, 2);
        dvr += __shfl_xor_sync(0xffffffffu, dvr, 2);

        float s = 0.0f;
        bool conv = false;
        if (val < 1e-20f) conv = true;
        else {
            float F0 = val - 1.0f;
            if (fabsf(F0) < 1e-6f) conv = true;
            else if (val > 1.0f)
                s = val * lg2f(val) / ((2.0f * L2E) * dvr);   // Jensen: F(s_ws) >= 0
        }
        for (int it = 0; it < 30; ++it) {
            if (__all_sync(0xffffffffu, conv)) break;
            float v = 0.0f, d = 0.0f;
            #pragma unroll
            for (int j = 0; j < 16; ++j) {
                float t = ex2f(Q[j] * s) * X2[j];
                v += t; d += R[j] * t;
            }
            v += __shfl_xor_sync(0xffffffffu, v, 1);
            d += __shfl_xor_sync(0xffffffffu, d, 1);
            v += __shfl_xor_sync(0xffffffffu, v, 2);
            d += __shfl_xor_sync(0xffffffffu, d, 2);
            float F = v - 1.0f;
            if (fabsf(F) < 1e-6f) conv = true;
            float den = -2.0f * d;
            den = (den == 0.0f) ? 1.0f : den;
            if (!conv) s -= __fdividef(F, den);
        }

        #pragma unroll
        for (int j = 0; j < 16; j += 2) {
            float xs0 = X[j]     * ex2f(Q[j]     * 0.5f * s);   // x * e^{-r s}
            float xs1 = X[j + 1] * ex2f(Q[j + 1] * 0.5f * s);
            *(uint32_t*)(sm + OFF_XS + U4(m, (cb + j) >> 1, 32)) = packh(xs0, xs1);
        }
        if ((lane & 3) == 0) esclp[m] = ex2f(L2E * s);
    }
    __syncthreads();

    const int g  = lane >> 2;
    const int tg = lane & 3;
    const int mw = wid & 1;      // 2 M tiles of 32
    const int nw = wid >> 1;     // 4 N tiles

    const int lr  = lane & 7, seg = lane >> 3;
    const int arow = mw * 32 + lr + ((seg & 1) << 3);
    const int apo  = (seg & 2) << 1;
    const int axor = (arow & 7) << 2;
    const int brow1 = nw * 64 + lr + ((seg >> 1) << 3);   // W1 rows 0..255
    const int bpo   = (seg & 1) << 2;
    const int bxor1 = (brow1 & 7) << 2;
    const int brow2 = nw * 16 + lr + ((seg >> 1) << 3);   // W2 rows 0..63
    const int bxor2 = (brow2 & 7) << 2;

    // ---- GEMM1: [64x256] = Xh[64x64] @ (W1h+W1l)^T, warp tile 32x64, pipelined ----
    float acc[2][8][4];
    #pragma unroll
    for (int mi = 0; mi < 2; ++mi)
        #pragma unroll
        for (int j = 0; j < 8; ++j)
            #pragma unroll
            for (int q = 0; q < 4; ++q) acc[mi][j][q] = 0.0f;

    {
        const uint32_t aB = smb + OFF_XS + arow * 128;
        uint32_t a0[4], a1[4], qh[4], ql[4];
        uint32_t a0n[4], a1n[4], qhn[4], qln[4];

        ldm_x4(a0, aB +        ((apo ^ axor) << 2));
        ldm_x4(a1, aB + 2048 + ((apo ^ axor) << 2));
        {
            uint32_t boff = brow1 * 128 + ((bpo ^ bxor1) << 2);
            ldm_x4(qh, smb + OFF_W1H + boff);
            ldm_x4(ql, smb + OFF_W1L + boff);
        }
        #pragma unroll
        for (int kb2 = 0; kb2 < 32; kb2 += 8) {
            #pragma unroll
            for (int jj = 0; jj < 4; ++jj) {
                // prefetch next (jj+1, or next kb2's jj=0 + A frags)
                if (jj < 3) {
                    uint32_t boff = (brow1 + (jj + 1) * 16) * 128 + (((kb2 + bpo) ^ bxor1) << 2);
                    ldm_x4(qhn, smb + OFF_W1H + boff);
                    ldm_x4(qln, smb + OFF_W1L + boff);
                } else if (kb2 < 24) {
                    uint32_t boff = brow1 * 128 + (((kb2 + 8 + bpo) ^ bxor1) << 2);
                    ldm_x4(qhn, smb + OFF_W1H + boff);
                    ldm_x4(qln, smb + OFF_W1L + boff);
                    ldm_x4(a0n, aB +        (((kb2 + 8 + apo) ^ axor) << 2));
                    ldm_x4(a1n, aB + 2048 + (((kb2 + 8 + apo) ^ axor) << 2));
                }
                mma16816(acc[0][2*jj],     a0, qh[0], qh[1]);
                mma16816(acc[1][2*jj],     a1, qh[0], qh[1]);
                mma16816(acc[0][2*jj + 1], a0, qh[2], qh[3]);
                mma16816(acc[1][2*jj + 1], a1, qh[2], qh[3]);
                mma16816(acc[0][2*jj],     a0, ql[0], ql[1]);
                mma16816(acc[1][2*jj],     a1, ql[0], ql[1]);
                mma16816(acc[0][2*jj + 1], a0, ql[2], ql[3]);
                mma16816(acc[1][2*jj + 1], a1, ql[2], ql[3]);
                cp4(qh, qhn); cp4(ql, qln);
                if (jj == 3) { cp4(a0, a0n); cp4(a1, a1n); }
            }
        }
    }

    // all warps done reading W1 before H overwrites its slot
    __syncthreads();

    // ---- epilogue1: +b1, relu -> H hi (swizzled [64][128 units], aliases W1H) ----
    #pragma unroll
    for (int mi = 0; mi < 2; ++mi) {
        int r0 = mw * 32 + mi * 16 + g;
        #pragma unroll
        for (int j = 0; j < 8; ++j) {
            int col = nw * 64 + j * 8 + 2 * tg;
            int p = col >> 1;
            float bb0 = b1s[col], bb1 = b1s[col + 1];
            float v0 = fmaxf(acc[mi][j][0] + bb0, 0.0f);
            float v1 = fmaxf(acc[mi][j][1] + bb1, 0.0f);
            float v2 = fmaxf(acc[mi][j][2] + bb0, 0.0f);
            float v3 = fmaxf(acc[mi][j][3] + bb1, 0.0f);
            *(uint32_t*)(sm + OFF_H + U4(r0,     p, 128)) = packh(v0, v1);
            *(uint32_t*)(sm + OFF_H + U4(r0 + 8, p, 128)) = packh(v2, v3);
        }
    }
    __syncthreads();

    // ---- GEMM2: [64x64] = Hh[64x256] @ W2h^T, warp tile 32x16, pipelined ----
    float acc2[2][2][4];
    #pragma unroll
    for (int mi = 0; mi < 2; ++mi)
        #pragma unroll
        for (int j = 0; j < 2; ++j)
            #pragma unroll
            for (int q = 0; q < 4; ++q) acc2[mi][j][q] = 0.0f;

    {
        const uint32_t aB = smb + OFF_H + arow * 512;
        const uint32_t bB = smb + OFF_W2H + brow2 * 512;
        uint32_t a0[4], a1[4], qh[4];
        uint32_t a0n[4], a1n[4], qhn[4];

        ldm_x4(a0, aB +        ((apo ^ axor) << 2));
        ldm_x4(a1, aB + 8192 + ((apo ^ axor) << 2));
        ldm_x4(qh, bB + ((bpo ^ bxor2) << 2));
        #pragma unroll
        for (int kb2 = 0; kb2 < 128; kb2 += 8) {
            if (kb2 < 120) {
                ldm_x4(a0n, aB +        (((kb2 + 8 + apo) ^ axor) << 2));
                ldm_x4(a1n, aB + 8192 + (((kb2 + 8 + apo) ^ axor) << 2));
                ldm_x4(qhn, bB + (((kb2 + 8 + bpo) ^ bxor2) << 2));
            }
            mma16816(acc2[0][0], a0, qh[0], qh[1]);
            mma16816(acc2[1][0], a1, qh[0], qh[1]);
            mma16816(acc2[0][1], a0, qh[2], qh[3]);
            mma16816(acc2[1][1], a1, qh[2], qh[3]);
            cp4(a0, a0n); cp4(a1, a1n); cp4(qh, qhn);
        }
    }

    // ---- epilogue2: +b2, * e^{s}, store ----
    #pragma unroll
    for (int mi = 0; mi < 2; ++mi) {
        int lr0 = mw * 32 + mi * 16 + g;
        int lr1 = lr0 + 8;
        float e0 = esclp[lr0], e1 = esclp[lr1];
        long long row0 = gb + lr0, row1 = gb + lr1;
        #pragma unroll
        for (int j = 0; j < 2; ++j) {
            int col = nw * 16 + j * 8 + 2 * tg;
            float bb0 = b2s[col], bb1 = b2s[col + 1];
            if (row0 < B)
                *(float2*)(out + row0 * 64 + col) =
                    make_float2((acc2[mi][j][0] + bb0) * e0, (acc2[mi][j][1] + bb1) * e0);
            if (row1 < B)
                *(float2*)(out + row1 * 64 + col) =
                    make_float2((acc2[mi][j][2] + bb0) * e1, (acc2[mi][j][3] + bb1) * e1);
        }
    }
}

extern "C" void kernel_launch(void* const* d_in, const int* in_sizes, int n_in,
                              void* d_out, int out_size) {
    const float* x  = (const float*)d_in[0];
    const float* r  = (const float*)d_in[1];
    const float* W1 = (const float*)d_in[2];
    const float* b1 = (const float*)d_in[3];
    const float* W2 = (const float*)d_in[4];
    const float* b2 = (const float*)d_in[5];
    float* out = (float*)d_out;

    const int B = in_sizes[0] / 64;
    const int grid = (B + TILE_B - 1) / TILE_B;

    prep_w_kernel<<<32, 256>>>(W1, W2);

    cudaFuncSetAttribute(aniso_mma_kernel,
                         cudaFuncAttributeMaxDynamicSharedMemorySize, SMEM_BYTES);
    aniso_mma_kernel<<<grid, THREADS, SMEM_BYTES>>>(x, r, b1, b2, out, B);
}

// round 11
// speedup vs baseline: 10.5136x; 1.2035x over previous
#include <cuda_runtime.h>
#include <cuda_fp16.h>
#include <cstdint>

#define THREADS 256
#define TILE_B  64

// ---------------- smem byte map (per CTA, 2 CTAs/SM) ----------------
// H (32KB) aliases W1H after GEMM1 completes (sync-separated).
#define OFF_XS  0          // Xs hi [64][64] f16, swizzled        8192
#define OFF_W1H 8192       // W1 hi [256][64]                    32768
#define OFF_W2H 40960      // W2 hi [64][256]                    32768
#define OFF_H   8192       // H hi  [64][256]  (aliases W1H)     32768
#define OFF_ES  73728      // escl 64 f32
#define OFF_B1  73984      // b1  256 f32
#define OFF_B2  75008      // b2   64 f32
#define SMEM_BYTES 75264

// Swizzled byte offset of 4B unit (row, p); c2 = units per row. XOR at 16B
// granularity -> ldmatrix-legal rows, conflict-free phases.
#define U4(row, p, c2) ((((row) * (c2)) + ((p) ^ (((row) & 7) << 2))) << 2)

// Pre-swizzled fp16 weights: [W1H | W2H], 32KB each.
__device__ __align__(16) unsigned char g_Wbuf[65536];

__device__ __forceinline__ float ex2f(float v) {
    float y; asm("ex2.approx.f32 %0, %1;" : "=f"(y) : "f"(v)); return y;
}
__device__ __forceinline__ float lg2f(float v) {
    float y; asm("lg2.approx.f32 %0, %1;" : "=f"(y) : "f"(v)); return y;
}
__device__ __forceinline__ uint32_t packh(float lo, float hi) {
    half2 h = __floats2half2_rn(lo, hi);          // lo -> low half
    return *(uint32_t*)&h;
}
__device__ __forceinline__ void mma16816(float* c, const uint32_t* a, uint32_t b0, uint32_t b1) {
    asm volatile(
        "mma.sync.aligned.m16n8k16.row.col.f32.f16.f16.f32 "
        "{%0,%1,%2,%3}, {%4,%5,%6,%7}, {%8,%9}, {%0,%1,%2,%3};"
        : "+f"(c[0]), "+f"(c[1]), "+f"(c[2]), "+f"(c[3])
        : "r"(a[0]), "r"(a[1]), "r"(a[2]), "r"(a[3]), "r"(b0), "r"(b1));
}
__device__ __forceinline__ void ldm_x4(uint32_t* d, uint32_t addr) {
    asm volatile("ldmatrix.sync.aligned.m8n8.x4.shared.b16 {%0,%1,%2,%3}, [%4];"
        : "=r"(d[0]), "=r"(d[1]), "=r"(d[2]), "=r"(d[3]) : "r"(addr));
}
__device__ __forceinline__ void cp4(uint32_t* d, const uint32_t* s) {
    d[0] = s[0]; d[1] = s[1]; d[2] = s[2]; d[3] = s[3];
}

// ---------------- prep kernel: W fp32 -> fp16 hi, swizzled ----------------
__global__ void prep_w_kernel(const float* __restrict__ W1, const float* __restrict__ W2) {
    int t = blockIdx.x * 256 + threadIdx.x;       // pair index 0..8191
    {
        float2 w = ((const float2*)W1)[t];
        half2 h = __floats2half2_rn(w.x, w.y);
        *(uint32_t*)(g_Wbuf + U4(t >> 5, t & 31, 32)) = *(uint32_t*)&h;
    }
    {
        float2 w = ((const float2*)W2)[t];
        half2 h = __floats2half2_rn(w.x, w.y);
        *(uint32_t*)(g_Wbuf + 32768 + U4(t >> 7, t & 127, 128)) = *(uint32_t*)&h;
    }
}

__global__ __launch_bounds__(THREADS, 2)
void aniso_mma_kernel(const float* __restrict__ x, const float* __restrict__ r,
                      const float* __restrict__ b1, const float* __restrict__ b2,
                      float* __restrict__ out, int B)
{
    extern __shared__ char sm[];
    uint32_t smb;
    asm("{ .reg .u64 t; cvta.to.shared.u64 t, %1; cvt.u32.u64 %0, t; }" : "=r"(smb) : "l"(sm));
    float* esclp = (float*)(sm + OFF_ES);
    float* b1s   = (float*)(sm + OFF_B1);
    float* b2s   = (float*)(sm + OFF_B2);

    const int tid  = threadIdx.x;
    const int lane = tid & 31;
    const int wid  = tid >> 5;
    const long long gb = (long long)blockIdx.x * TILE_B;

    b1s[tid] = b1[tid & 255];
    if (tid < 64) b2s[tid] = b2[tid];

    // ---- copy W1h|W2h (64KB) into smem ----
    #pragma unroll
    for (int i = 0; i < 16; ++i) {
        int u = tid + i * THREADS;                // 0..4095 uint4s
        *(uint4*)(sm + OFF_W1H + (u << 4)) = ((const uint4*)g_Wbuf)[u];
    }

    // ---- Newton: 4-lane group per sample; warm start (<= root) ----
    {
        const float L2E = 1.4426950408889634f;
        const int sg = lane >> 2;
        const int cb = (lane & 3) << 4;
        const int m  = wid * 8 + sg;              // 0..63
        long long row = gb + m; if (row >= B) row = B - 1;

        float X[16], X2[16], Q[16], R[16];
        #pragma unroll
        for (int q4 = 0; q4 < 4; ++q4) {
            float4 v = *(const float4*)(x + row * 64 + cb + q4 * 4);
            X[q4*4+0] = v.x; X[q4*4+1] = v.y; X[q4*4+2] = v.z; X[q4*4+3] = v.w;
            float4 rv = *(const float4*)(r + cb + q4 * 4);
            R[q4*4+0] = rv.x; R[q4*4+1] = rv.y; R[q4*4+2] = rv.z; R[q4*4+3] = rv.w;
        }
        #pragma unroll
        for (int j = 0; j < 16; ++j) { X2[j] = X[j] * X[j]; Q[j] = -2.0f * L2E * R[j]; }

        float val = 0.0f, dvr = 0.0f;
        #pragma unroll
        for (int j = 0; j < 16; ++j) { val += X2[j]; dvr += R[j] * X2[j]; }
        val += __shfl_xor_sync(0xffffffffu, val, 1);
        dvr += __shfl_xor_sync(0xffffffffu, dvr, 1);
        val += __shfl_xor_sync(0xffffffffu, val, 2);
        dvr += __shfl_xor_sync(0xffffffffu, dvr, 2);

        float s = 0.0f;
        bool conv = false;
        if (val < 1e-20f) conv = true;
        else {
            float F0 = val - 1.0f;
            if (fabsf(F0) < 1e-6f) conv = true;
            else if (val > 1.0f)
                s = val * lg2f(val) / ((2.0f * L2E) * dvr);   // Jensen: F(s_ws) >= 0
        }
        for (int it = 0; it < 30; ++it) {
            if (__all_sync(0xffffffffu, conv)) break;
            float v = 0.0f, d = 0.0f;
            #pragma unroll
            for (int j = 0; j < 16; ++j) {
                float t = ex2f(Q[j] * s) * X2[j];
                v += t; d += R[j] * t;
            }
            v += __shfl_xor_sync(0xffffffffu, v, 1);
            d += __shfl_xor_sync(0xffffffffu, d, 1);
            v += __shfl_xor_sync(0xffffffffu, v, 2);
            d += __shfl_xor_sync(0xffffffffu, d, 2);
            float F = v - 1.0f;
            if (fabsf(F) < 1e-6f) conv = true;
            float den = -2.0f * d;
            den = (den == 0.0f) ? 1.0f : den;
            if (!conv) s -= __fdividef(F, den);
        }

        #pragma unroll
        for (int j = 0; j < 16; j += 2) {
            float xs0 = X[j]     * ex2f(Q[j]     * 0.5f * s);   // x * e^{-r s}
            float xs1 = X[j + 1] * ex2f(Q[j + 1] * 0.5f * s);
            *(uint32_t*)(sm + OFF_XS + U4(m, (cb + j) >> 1, 32)) = packh(xs0, xs1);
        }
        if ((lane & 3) == 0) esclp[m] = ex2f(L2E * s);
    }
    __syncthreads();

    const int g  = lane >> 2;
    const int tg = lane & 3;
    const int mw = wid & 1;      // 2 M tiles of 32
    const int nw = wid >> 1;     // 4 N tiles

    const int lr  = lane & 7, seg = lane >> 3;
    const int arow = mw * 32 + lr + ((seg & 1) << 3);
    const int apo  = (seg & 2) << 1;
    const int axor = (arow & 7) << 2;
    const int brow1 = nw * 64 + lr + ((seg >> 1) << 3);   // W1 rows 0..255
    const int bpo   = (seg & 1) << 2;
    const int bxor1 = (brow1 & 7) << 2;
    const int brow2 = nw * 16 + lr + ((seg >> 1) << 3);   // W2 rows 0..63
    const int bxor2 = (brow2 & 7) << 2;

    // ---- GEMM1: [64x256] = Xh[64x64] @ W1h^T, warp tile 32x64, pipelined ----
    float acc[2][8][4];
    #pragma unroll
    for (int mi = 0; mi < 2; ++mi)
        #pragma unroll
        for (int j = 0; j < 8; ++j)
            #pragma unroll
            for (int q = 0; q < 4; ++q) acc[mi][j][q] = 0.0f;

    {
        const uint32_t aB = smb + OFF_XS + arow * 128;
        uint32_t a0[4], a1[4], qh[4];
        uint32_t a0n[4], a1n[4], qhn[4];

        ldm_x4(a0, aB +        ((apo ^ axor) << 2));
        ldm_x4(a1, aB + 2048 + ((apo ^ axor) << 2));
        ldm_x4(qh, smb + OFF_W1H + brow1 * 128 + ((bpo ^ bxor1) << 2));
        #pragma unroll
        for (int kb2 = 0; kb2 < 32; kb2 += 8) {
            #pragma unroll
            for (int jj = 0; jj < 4; ++jj) {
                if (jj < 3) {
                    ldm_x4(qhn, smb + OFF_W1H + (brow1 + (jj + 1) * 16) * 128
                                  + (((kb2 + bpo) ^ bxor1) << 2));
                } else if (kb2 < 24) {
                    ldm_x4(qhn, smb + OFF_W1H + brow1 * 128
                                  + (((kb2 + 8 + bpo) ^ bxor1) << 2));
                    ldm_x4(a0n, aB +        (((kb2 + 8 + apo) ^ axor) << 2));
                    ldm_x4(a1n, aB + 2048 + (((kb2 + 8 + apo) ^ axor) << 2));
                }
                mma16816(acc[0][2*jj],     a0, qh[0], qh[1]);
                mma16816(acc[1][2*jj],     a1, qh[0], qh[1]);
                mma16816(acc[0][2*jj + 1], a0, qh[2], qh[3]);
                mma16816(acc[1][2*jj + 1], a1, qh[2], qh[3]);
                cp4(qh, qhn);
                if (jj == 3) { cp4(a0, a0n); cp4(a1, a1n); }
            }
        }
    }

    // all warps done reading W1 before H overwrites its slot
    __syncthreads();

    // ---- epilogue1: +b1, relu -> H hi (swizzled [64][128 units], aliases W1H) ----
    #pragma unroll
    for (int mi = 0; mi < 2; ++mi) {
        int r0 = mw * 32 + mi * 16 + g;
        #pragma unroll
        for (int j = 0; j < 8; ++j) {
            int col = nw * 64 + j * 8 + 2 * tg;
            int p = col >> 1;
            float bb0 = b1s[col], bb1 = b1s[col + 1];
            float v0 = fmaxf(acc[mi][j][0] + bb0, 0.0f);
            float v1 = fmaxf(acc[mi][j][1] + bb1, 0.0f);
            float v2 = fmaxf(acc[mi][j][2] + bb0, 0.0f);
            float v3 = fmaxf(acc[mi][j][3] + bb1, 0.0f);
            *(uint32_t*)(sm + OFF_H + U4(r0,     p, 128)) = packh(v0, v1);
            *(uint32_t*)(sm + OFF_H + U4(r0 + 8, p, 128)) = packh(v2, v3);
        }
    }
    __syncthreads();

    // ---- GEMM2: [64x64] = Hh[64x256] @ W2h^T, warp tile 32x16, pipelined ----
    float acc2[2][2][4];
    #pragma unroll
    for (int mi = 0; mi < 2; ++mi)
        #pragma unroll
        for (int j = 0; j < 2; ++j)
            #pragma unroll
            for (int q = 0; q < 4; ++q) acc2[mi][j][q] = 0.0f;

    {
        const uint32_t aB = smb + OFF_H + arow * 512;
        const uint32_t bB = smb + OFF_W2H + brow2 * 512;
        uint32_t a0[4], a1[4], qh[4];
        uint32_t a0n[4], a1n[4], qhn[4];

        ldm_x4(a0, aB +        ((apo ^ axor) << 2));
        ldm_x4(a1, aB + 8192 + ((apo ^ axor) << 2));
        ldm_x4(qh, bB + ((bpo ^ bxor2) << 2));
        #pragma unroll
        for (int kb2 = 0; kb2 < 128; kb2 += 8) {
            if (kb2 < 120) {
                ldm_x4(a0n, aB +        (((kb2 + 8 + apo) ^ axor) << 2));
                ldm_x4(a1n, aB + 8192 + (((kb2 + 8 + apo) ^ axor) << 2));
                ldm_x4(qhn, bB + (((kb2 + 8 + bpo) ^ bxor2) << 2));
            }
            mma16816(acc2[0][0], a0, qh[0], qh[1]);
            mma16816(acc2[1][0], a1, qh[0], qh[1]);
            mma16816(acc2[0][1], a0, qh[2], qh[3]);
            mma16816(acc2[1][1], a1, qh[2], qh[3]);
            cp4(a0, a0n); cp4(a1, a1n); cp4(qh, qhn);
        }
    }

    // ---- epilogue2: +b2, * e^{s}, store ----
    #pragma unroll
    for (int mi = 0; mi < 2; ++mi) {
        int lr0 = mw * 32 + mi * 16 + g;
        int lr1 = lr0 + 8;
        float e0 = esclp[lr0], e1 = esclp[lr1];
        long long row0 = gb + lr0, row1 = gb + lr1;
        #pragma unroll
        for (int j = 0; j < 2; ++j) {
            int col = nw * 16 + j * 8 + 2 * tg;
            float bb0 = b2s[col], bb1 = b2s[col + 1];
            if (row0 < B)
                *(float2*)(out + row0 * 64 + col) =
                    make_float2((acc2[mi][j][0] + bb0) * e0, (acc2[mi][j][1] + bb1) * e0);
            if (row1 < B)
                *(float2*)(out + row1 * 64 + col) =
                    make_float2((acc2[mi][j][2] + bb0) * e1, (acc2[mi][j][3] + bb1) * e1);
        }
    }
}

extern "C" void kernel_launch(void* const* d_in, const int* in_sizes, int n_in,
                              void* d_out, int out_size) {
    const float* x  = (const float*)d_in[0];
    const float* r  = (const float*)d_in[1];
    const float* W1 = (const float*)d_in[2];
    const float* b1 = (const float*)d_in[3];
    const float* W2 = (const float*)d_in[4];
    const float* b2 = (const float*)d_in[5];
    float* out = (float*)d_out;

    const int B = in_sizes[0] / 64;
    const int grid = (B + TILE_B - 1) / TILE_B;

    prep_w_kernel<<<32, 256>>>(W1, W2);

    cudaFuncSetAttribute(aniso_mma_kernel,
                         cudaFuncAttributeMaxDynamicSharedMemorySize, SMEM_BYTES);
    aniso_mma_kernel<<<grid, THREADS, SMEM_BYTES>>>(x, r, b1, b2, out, B);
}

// round 14
// speedup vs baseline: 11.9079x; 1.1326x over previous
#include <cuda_runtime.h>
#include <cuda_fp16.h>
#include <cstdint>

#define THREADS 256
#define TILE_B  64

// ---------------- smem byte map (per CTA, 2 CTAs/SM) ----------------
#define OFF_XS  0          // Xs hi [64][64] f16, swizzled        8192
#define OFF_H   8192       // H hi  [64][256] f16                32768
#define OFF_ES  40960      // escl 64 f32
#define OFF_B1  41216      // b1  256 f32
#define OFF_B2  42240      // b2   64 f32
#define SMEM_BYTES 42496

// Swizzled byte offset of 4B unit (row, p); c2 = units per row. XOR at 16B
// granularity -> ldmatrix-legal rows, conflict-free phases.
#define U4(row, p, c2) ((((row) * (c2)) + ((p) ^ (((row) & 7) << 2))) << 2)

// W in mma B-FRAGMENT order (one uint4 per lane per 16x16 tile):
//   [0,32KB):  W1 frags, slot(nw,kb,jj) = nw*16 + kb*4 + jj   (nw,kb,jj in 0..3)
//   [32,64KB): W2 frags, slot(nw,kb)    = nw*16 + kb          (nw 0..3, kb 0..15)
// Per slot: 32 lanes x uint4 = {n0+g:(k,k+1), n0+g:(k+8,k+9), n0+8+g:(k,k+1), n0+8+g:(k+8,k+9)}
// 64 slots/half x 32 lanes = 2048 uint4 per half -> prep MUST use exactly 2048 threads.
__device__ __align__(16) unsigned char g_Wbuf[65536];

__device__ __forceinline__ float ex2f(float v) {
    float y; asm("ex2.approx.f32 %0, %1;" : "=f"(y) : "f"(v)); return y;
}
__device__ __forceinline__ float lg2f(float v) {
    float y; asm("lg2.approx.f32 %0, %1;" : "=f"(y) : "f"(v)); return y;
}
__device__ __forceinline__ uint32_t packh(float lo, float hi) {
    half2 h = __floats2half2_rn(lo, hi);          // lo -> low 16 bits
    return *(uint32_t*)&h;
}
__device__ __forceinline__ void mma16816(float* c, const uint32_t* a, uint32_t b0, uint32_t b1) {
    asm volatile(
        "mma.sync.aligned.m16n8k16.row.col.f32.f16.f16.f32 "
        "{%0,%1,%2,%3}, {%4,%5,%6,%7}, {%8,%9}, {%0,%1,%2,%3};"
        : "+f"(c[0]), "+f"(c[1]), "+f"(c[2]), "+f"(c[3])
        : "r"(a[0]), "r"(a[1]), "r"(a[2]), "r"(a[3]), "r"(b0), "r"(b1));
}
__device__ __forceinline__ void ldm_x4(uint32_t* d, uint32_t addr) {
    asm volatile("ldmatrix.sync.aligned.m8n8.x4.shared.b16 {%0,%1,%2,%3}, [%4];"
        : "=r"(d[0]), "=r"(d[1]), "=r"(d[2]), "=r"(d[3]) : "r"(addr));
}
__device__ __forceinline__ void cp4(uint32_t* d, const uint32_t* s) {
    d[0] = s[0]; d[1] = s[1]; d[2] = s[2]; d[3] = s[3];
}

// ---------------- prep kernel: W fp32 -> fp16 B-fragments (2048 threads!) ----
__global__ void prep_w_kernel(const float* __restrict__ W1, const float* __restrict__ W2) {
    int idx = blockIdx.x * 256 + threadIdx.x;     // 0..2047 (one per uint4 slot-entry)
    int lane = idx & 31, g = lane >> 2, tg = lane & 3;
    {   // W1 [256 n][64 k] -> frag slots (nw,kb,jj)
        int jj = (idx >> 5) & 3, kb = (idx >> 7) & 3, nw = (idx >> 9) & 3;
        int n = nw * 64 + jj * 16 + g;
        int k = kb * 16 + 2 * tg;
        uint4 v;
        v.x = packh(W1[n * 64 + k],           W1[n * 64 + k + 1]);
        v.y = packh(W1[n * 64 + k + 8],       W1[n * 64 + k + 9]);
        v.z = packh(W1[(n + 8) * 64 + k],     W1[(n + 8) * 64 + k + 1]);
        v.w = packh(W1[(n + 8) * 64 + k + 8], W1[(n + 8) * 64 + k + 9]);
        ((uint4*)g_Wbuf)[idx] = v;
    }
    {   // W2 [64 n][256 k] -> frag slots (nw,kb)
        int kb = (idx >> 5) & 15, nw = (idx >> 9) & 3;
        int n = nw * 16 + g;
        int k = kb * 16 + 2 * tg;
        uint4 v;
        v.x = packh(W2[n * 256 + k],           W2[n * 256 + k + 1]);
        v.y = packh(W2[n * 256 + k + 8],       W2[n * 256 + k + 9]);
        v.z = packh(W2[(n + 8) * 256 + k],     W2[(n + 8) * 256 + k + 1]);
        v.w = packh(W2[(n + 8) * 256 + k + 8], W2[(n + 8) * 256 + k + 9]);
        ((uint4*)(g_Wbuf + 32768))[idx] = v;
    }
}

__global__ __launch_bounds__(THREADS, 2)
void aniso_mma_kernel(const float* __restrict__ x, const float* __restrict__ r,
                      const float* __restrict__ b1, const float* __restrict__ b2,
                      float* __restrict__ out, int B)
{
    extern __shared__ char sm[];
    uint32_t smb;
    asm("{ .reg .u64 t; cvta.to.shared.u64 t, %1; cvt.u32.u64 %0, t; }" : "=r"(smb) : "l"(sm));
    float* esclp = (float*)(sm + OFF_ES);
    float* b1s   = (float*)(sm + OFF_B1);
    float* b2s   = (float*)(sm + OFF_B2);

    const int tid  = threadIdx.x;
    const int lane = tid & 31;
    const int wid  = tid >> 5;
    const long long gb = (long long)blockIdx.x * TILE_B;

    b1s[tid] = b1[tid & 255];
    if (tid < 64) b2s[tid] = b2[tid];

    // ---- Newton: 4-lane group per sample; warm start (<= root) ----
    {
        const float L2E = 1.4426950408889634f;
        const int sg = lane >> 2;
        const int cb = (lane & 3) << 4;
        const int m  = wid * 8 + sg;              // 0..63
        long long row = gb + m; if (row >= B) row = B - 1;

        float X[16], X2[16], Q[16], R[16];
        #pragma unroll
        for (int q4 = 0; q4 < 4; ++q4) {
            float4 v = *(const float4*)(x + row * 64 + cb + q4 * 4);
            X[q4*4+0] = v.x; X[q4*4+1] = v.y; X[q4*4+2] = v.z; X[q4*4+3] = v.w;
            float4 rv = *(const float4*)(r + cb + q4 * 4);
            R[q4*4+0] = rv.x; R[q4*4+1] = rv.y; R[q4*4+2] = rv.z; R[q4*4+3] = rv.w;
        }
        #pragma unroll
        for (int j = 0; j < 16; ++j) { X2[j] = X[j] * X[j]; Q[j] = -2.0f * L2E * R[j]; }

        float val = 0.0f, dvr = 0.0f;
        #pragma unroll
        for (int j = 0; j < 16; ++j) { val += X2[j]; dvr += R[j] * X2[j]; }
        val += __shfl_xor_sync(0xffffffffu, val, 1);
        dvr += __shfl_xor_sync(0xffffffffu, dvr, 1);
        val += __shfl_xor_sync(0xffffffffu, val, 2);
        dvr += __shfl_xor_sync(0xffffffffu, dvr, 2);

        float s = 0.0f;
        bool conv = false;
        if (val < 1e-20f) conv = true;
        else {
            float F0 = val - 1.0f;
            if (fabsf(F0) < 1e-6f) conv = true;
            else if (val > 1.0f)
                s = val * lg2f(val) / ((2.0f * L2E) * dvr);   // Jensen: F(s_ws) >= 0
        }
        for (int it = 0; it < 30; ++it) {
            if (__all_sync(0xffffffffu, conv)) break;
            float v = 0.0f, d = 0.0f;
            #pragma unroll
            for (int j = 0; j < 16; ++j) {
                float t = ex2f(Q[j] * s) * X2[j];
                v += t; d += R[j] * t;
            }
            v += __shfl_xor_sync(0xffffffffu, v, 1);
            d += __shfl_xor_sync(0xffffffffu, d, 1);
            v += __shfl_xor_sync(0xffffffffu, v, 2);
            d += __shfl_xor_sync(0xffffffffu, d, 2);
            float F = v - 1.0f;
            if (fabsf(F) < 1e-6f) conv = true;
            float den = -2.0f * d;
            den = (den == 0.0f) ? 1.0f : den;
            if (!conv) s -= __fdividef(F, den);
        }

        #pragma unroll
        for (int j = 0; j < 16; j += 2) {
            float xs0 = X[j]     * ex2f(Q[j]     * 0.5f * s);   // x * e^{-r s}
            float xs1 = X[j + 1] * ex2f(Q[j + 1] * 0.5f * s);
            *(uint32_t*)(sm + OFF_XS + U4(m, (cb + j) >> 1, 32)) = packh(xs0, xs1);
        }
        if ((lane & 3) == 0) esclp[m] = ex2f(L2E * s);
    }
    __syncthreads();

    const int g  = lane >> 2;
    const int tg = lane & 3;
    const int mw = wid & 1;      // 2 M tiles of 32
    const int nw = wid >> 1;     // 4 N tiles

    const int lr  = lane & 7, seg = lane >> 3;
    const int arow = mw * 32 + lr + ((seg & 1) << 3);
    const int apo  = (seg & 2) << 1;
    const int axor = (arow & 7) << 2;

    const uint4* Wf1 = (const uint4*)g_Wbuf + nw * 512;          // 16 slots x 32
    const uint4* Wf2 = (const uint4*)(g_Wbuf + 32768) + nw * 512;

    // ---- GEMM1: [64x256] = Xh[64x64] @ W1h^T, warp tile 32x64, pipelined ----
    float acc[2][8][4];
    #pragma unroll
    for (int mi = 0; mi < 2; ++mi)
        #pragma unroll
        for (int j = 0; j < 8; ++j)
            #pragma unroll
            for (int q = 0; q < 4; ++q) acc[mi][j][q] = 0.0f;

    {
        const uint32_t aB = smb + OFF_XS + arow * 128;
        uint32_t a0[4], a1[4];
        uint32_t a0n[4], a1n[4];
        uint4 q, qn;

        ldm_x4(a0, aB +        ((apo ^ axor) << 2));
        ldm_x4(a1, aB + 2048 + ((apo ^ axor) << 2));
        q = __ldg(Wf1 + lane);
        #pragma unroll
        for (int kb = 0; kb < 4; ++kb) {
            #pragma unroll
            for (int jj = 0; jj < 4; ++jj) {
                int slot = kb * 4 + jj;
                if (slot < 15) qn = __ldg(Wf1 + ((slot + 1) << 5) + lane);
                if (jj == 3 && kb < 3) {
                    int kb2 = (kb + 1) * 8;
                    ldm_x4(a0n, aB +        (((kb2 + apo) ^ axor) << 2));
                    ldm_x4(a1n, aB + 2048 + (((kb2 + apo) ^ axor) << 2));
                }
                mma16816(acc[0][2*jj],     a0, q.x, q.y);
                mma16816(acc[1][2*jj],     a1, q.x, q.y);
                mma16816(acc[0][2*jj + 1], a0, q.z, q.w);
                mma16816(acc[1][2*jj + 1], a1, q.z, q.w);
                q = qn;
                if (jj == 3) { cp4(a0, a0n); cp4(a1, a1n); }
            }
        }
    }

    // ---- epilogue1: +b1, relu -> H hi (swizzled [64][128 units]) ----
    #pragma unroll
    for (int mi = 0; mi < 2; ++mi) {
        int r0 = mw * 32 + mi * 16 + g;
        #pragma unroll
        for (int j = 0; j < 8; ++j) {
            int col = nw * 64 + j * 8 + 2 * tg;
            int p = col >> 1;
            float bb0 = b1s[col], bb1 = b1s[col + 1];
            float v0 = fmaxf(acc[mi][j][0] + bb0, 0.0f);
            float v1 = fmaxf(acc[mi][j][1] + bb1, 0.0f);
            float v2 = fmaxf(acc[mi][j][2] + bb0, 0.0f);
            float v3 = fmaxf(acc[mi][j][3] + bb1, 0.0f);
            *(uint32_t*)(sm + OFF_H + U4(r0,     p, 128)) = packh(v0, v1);
            *(uint32_t*)(sm + OFF_H + U4(r0 + 8, p, 128)) = packh(v2, v3);
        }
    }
    __syncthreads();

    // ---- GEMM2: [64x64] = Hh[64x256] @ W2h^T, warp tile 32x16, pipelined ----
    float acc2[2][2][4];
    #pragma unroll
    for (int mi = 0; mi < 2; ++mi)
        #pragma unroll
        for (int j = 0; j < 2; ++j)
            #pragma unroll
            for (int q = 0; q < 4; ++q) acc2[mi][j][q] = 0.0f;

    {
        const uint32_t aB = smb + OFF_H + arow * 512;
        uint32_t a0[4], a1[4];
        uint32_t a0n[4], a1n[4];
        uint4 q, qn;

        ldm_x4(a0, aB +        ((apo ^ axor) << 2));
        ldm_x4(a1, aB + 8192 + ((apo ^ axor) << 2));
        q = __ldg(Wf2 + lane);
        #pragma unroll
        for (int kb = 0; kb < 16; ++kb) {
            if (kb < 15) {
                int kb2 = (kb + 1) * 8;
                qn = __ldg(Wf2 + ((kb + 1) << 5) + lane);
                ldm_x4(a0n, aB +        (((kb2 + apo) ^ axor) << 2));
                ldm_x4(a1n, aB + 8192 + (((kb2 + apo) ^ axor) << 2));
            }
            mma16816(acc2[0][0], a0, q.x, q.y);
            mma16816(acc2[1][0], a1, q.x, q.y);
            mma16816(acc2[0][1], a0, q.z, q.w);
            mma16816(acc2[1][1], a1, q.z, q.w);
            q = qn;
            cp4(a0, a0n); cp4(a1, a1n);
        }
    }

    // ---- epilogue2: +b2, * e^{s}, store ----
    #pragma unroll
    for (int mi = 0; mi < 2; ++mi) {
        int lr0 = mw * 32 + mi * 16 + g;
        int lr1 = lr0 + 8;
        float e0 = esclp[lr0], e1 = esclp[lr1];
        long long row0 = gb + lr0, row1 = gb + lr1;
        #pragma unroll
        for (int j = 0; j < 2; ++j) {
            int col = nw * 16 + j * 8 + 2 * tg;
            float bb0 = b2s[col], bb1 = b2s[col + 1];
            if (row0 < B)
                *(float2*)(out + row0 * 64 + col) =
                    make_float2((acc2[mi][j][0] + bb0) * e0, (acc2[mi][j][1] + bb1) * e0);
            if (row1 < B)
                *(float2*)(out + row1 * 64 + col) =
                    make_float2((acc2[mi][j][2] + bb0) * e1, (acc2[mi][j][3] + bb1) * e1);
        }
    }
}

extern "C" void kernel_launch(void* const* d_in, const int* in_sizes, int n_in,
                              void* d_out, int out_size) {
    const float* x  = (const float*)d_in[0];
    const float* r  = (const float*)d_in[1];
    const float* W1 = (const float*)d_in[2];
    const float* b1 = (const float*)d_in[3];
    const float* W2 = (const float*)d_in[4];
    const float* b2 = (const float*)d_in[5];
    float* out = (float*)d_out;

    const int B = in_sizes[0] / 64;
    const int grid = (B + TILE_B - 1) / TILE_B;

    prep_w_kernel<<<8, 256>>>(W1, W2);   // exactly 2048 threads = 2048 uint4 per half

    cudaFuncSetAttribute(aniso_mma_kernel,
                         cudaFuncAttributeMaxDynamicSharedMemorySize, SMEM_BYTES);
    aniso_mma_kernel<<<grid, THREADS, SMEM_BYTES>>>(x, r, b1, b2, out, B);
}

// round 15
// speedup vs baseline: 13.4915x; 1.1330x over previous
#include <cuda_runtime.h>
#include <cuda_fp16.h>
#include <cstdint>

#define THREADS 256
#define TILE_B  64

// ---------------- smem byte map (per CTA, 3 CTAs/SM) ----------------
#define OFF_XS  0          // Xs hi [64][64] f16, swizzled        8192
#define OFF_H   8192       // H hi  [64][256] f16                32768
#define OFF_ES  40960      // escl 64 f32                          256
#define OFF_B1  41216      // b1 as half2 [128]                    512
#define OFF_B2  41728      // b2   64 f32                          256
#define SMEM_BYTES 41984

// Swizzled byte offset of 4B unit (row, p); c2 = units per row. XOR at 16B
// granularity -> ldmatrix-legal rows, conflict-free phases.
#define U4(row, p, c2) ((((row) * (c2)) + ((p) ^ (((row) & 7) << 2))) << 2)

// W in mma B-FRAGMENT order (one uint4 per lane per 16x16 tile):
//   [0,32KB):  W1 frags, slot(nw,kb,jj) = nw*16 + kb*4 + jj   (nw,kb,jj in 0..3)
//   [32,64KB): W2 frags, slot(nw,kb)    = nw*16 + kb          (nw 0..3, kb 0..15)
// Per slot: 32 lanes x uint4 = {n0+g:(k,k+1), n0+g:(k+8,k+9), n0+8+g:(k,k+1), n0+8+g:(k+8,k+9)}
// 64 slots/half x 32 lanes = 2048 uint4 per half -> prep MUST use exactly 2048 threads.
__device__ __align__(16) unsigned char g_Wbuf[65536];

__device__ __forceinline__ float ex2f(float v) {
    float y; asm("ex2.approx.f32 %0, %1;" : "=f"(y) : "f"(v)); return y;
}
__device__ __forceinline__ float lg2f(float v) {
    float y; asm("lg2.approx.f32 %0, %1;" : "=f"(y) : "f"(v)); return y;
}
__device__ __forceinline__ uint32_t packh(float lo, float hi) {
    half2 h = __floats2half2_rn(lo, hi);          // lo -> low 16 bits
    return *(uint32_t*)&h;
}
__device__ __forceinline__ void mma16816(float* c, const uint32_t* a, uint32_t b0, uint32_t b1) {
    asm volatile(
        "mma.sync.aligned.m16n8k16.row.col.f32.f16.f16.f32 "
        "{%0,%1,%2,%3}, {%4,%5,%6,%7}, {%8,%9}, {%0,%1,%2,%3};"
        : "+f"(c[0]), "+f"(c[1]), "+f"(c[2]), "+f"(c[3])
        : "r"(a[0]), "r"(a[1]), "r"(a[2]), "r"(a[3]), "r"(b0), "r"(b1));
}
__device__ __forceinline__ void ldm_x4(uint32_t* d, uint32_t addr) {
    asm volatile("ldmatrix.sync.aligned.m8n8.x4.shared.b16 {%0,%1,%2,%3}, [%4];"
        : "=r"(d[0]), "=r"(d[1]), "=r"(d[2]), "=r"(d[3]) : "r"(addr));
}
__device__ __forceinline__ void cp4(uint32_t* d, const uint32_t* s) {
    d[0] = s[0]; d[1] = s[1]; d[2] = s[2]; d[3] = s[3];
}

// ---------------- prep kernel: W fp32 -> fp16 B-fragments (2048 threads!) ----
__global__ void prep_w_kernel(const float* __restrict__ W1, const float* __restrict__ W2) {
    int idx = blockIdx.x * 256 + threadIdx.x;     // 0..2047 (one per uint4 slot-entry)
    int lane = idx & 31, g = lane >> 2, tg = lane & 3;
    {   // W1 [256 n][64 k] -> frag slots (nw,kb,jj)
        int jj = (idx >> 5) & 3, kb = (idx >> 7) & 3, nw = (idx >> 9) & 3;
        int n = nw * 64 + jj * 16 + g;
        int k = kb * 16 + 2 * tg;
        uint4 v;
        v.x = packh(W1[n * 64 + k],           W1[n * 64 + k + 1]);
        v.y = packh(W1[n * 64 + k + 8],       W1[n * 64 + k + 9]);
        v.z = packh(W1[(n + 8) * 64 + k],     W1[(n + 8) * 64 + k + 1]);
        v.w = packh(W1[(n + 8) * 64 + k + 8], W1[(n + 8) * 64 + k + 9]);
        ((uint4*)g_Wbuf)[idx] = v;
    }
    {   // W2 [64 n][256 k] -> frag slots (nw,kb)
        int kb = (idx >> 5) & 15, nw = (idx >> 9) & 3;
        int n = nw * 16 + g;
        int k = kb * 16 + 2 * tg;
        uint4 v;
        v.x = packh(W2[n * 256 + k],           W2[n * 256 + k + 1]);
        v.y = packh(W2[n * 256 + k + 8],       W2[n * 256 + k + 9]);
        v.z = packh(W2[(n + 8) * 256 + k],     W2[(n + 8) * 256 + k + 1]);
        v.w = packh(W2[(n + 8) * 256 + k + 8], W2[(n + 8) * 256 + k + 9]);
        ((uint4*)(g_Wbuf + 32768))[idx] = v;
    }
}

__global__ __launch_bounds__(THREADS, 3)
void aniso_mma_kernel(const float* __restrict__ x, const float* __restrict__ r,
                      const float* __restrict__ b1, const float* __restrict__ b2,
                      float* __restrict__ out, int B)
{
    extern __shared__ char sm[];
    uint32_t smb;
    asm("{ .reg .u64 t; cvta.to.shared.u64 t, %1; cvt.u32.u64 %0, t; }" : "=r"(smb) : "l"(sm));
    float*  esclp = (float*)(sm + OFF_ES);
    __half2* b1h2 = (__half2*)(sm + OFF_B1);
    float*  b2s   = (float*)(sm + OFF_B2);

    const int tid  = threadIdx.x;
    const int lane = tid & 31;
    const int wid  = tid >> 5;
    const long long gb = (long long)blockIdx.x * TILE_B;

    if (tid < 128) b1h2[tid] = __floats2half2_rn(b1[2 * tid], b1[2 * tid + 1]);
    if (tid < 64)  b2s[tid] = b2[tid];

    // ---- Newton: 4-lane group per sample; warm start (<= root) ----
    {
        const float L2E = 1.4426950408889634f;
        const int sg = lane >> 2;
        const int cb = (lane & 3) << 4;
        const int m  = wid * 8 + sg;              // 0..63
        long long row = gb + m; if (row >= B) row = B - 1;

        float X[16], X2[16], R[16];
        #pragma unroll
        for (int q4 = 0; q4 < 4; ++q4) {
            float4 v = *(const float4*)(x + row * 64 + cb + q4 * 4);
            X[q4*4+0] = v.x; X[q4*4+1] = v.y; X[q4*4+2] = v.z; X[q4*4+3] = v.w;
            float4 rv = *(const float4*)(r + cb + q4 * 4);
            R[q4*4+0] = rv.x; R[q4*4+1] = rv.y; R[q4*4+2] = rv.z; R[q4*4+3] = rv.w;
        }
        #pragma unroll
        for (int j = 0; j < 16; ++j) X2[j] = X[j] * X[j];

        float val = 0.0f, dvr = 0.0f;
        #pragma unroll
        for (int j = 0; j < 16; ++j) { val += X2[j]; dvr += R[j] * X2[j]; }
        val += __shfl_xor_sync(0xffffffffu, val, 1);
        dvr += __shfl_xor_sync(0xffffffffu, dvr, 1);
        val += __shfl_xor_sync(0xffffffffu, val, 2);
        dvr += __shfl_xor_sync(0xffffffffu, dvr, 2);

        float s = 0.0f;
        bool conv = false;
        if (val < 1e-20f) conv = true;
        else {
            float F0 = val - 1.0f;
            if (fabsf(F0) < 1e-6f) conv = true;
            else if (val > 1.0f)
                s = val * lg2f(val) / ((2.0f * L2E) * dvr);   // Jensen: F(s_ws) >= 0
        }
        for (int it = 0; it < 30; ++it) {
            if (__all_sync(0xffffffffu, conv)) break;
            float c = (-2.0f * L2E) * s;          // e^{-2 r s} = 2^{r*c}
            float v = 0.0f, d = 0.0f;
            #pragma unroll
            for (int j = 0; j < 16; ++j) {
                float t = ex2f(R[j] * c) * X2[j];
                v += t; d += R[j] * t;
            }
            v += __shfl_xor_sync(0xffffffffu, v, 1);
            d += __shfl_xor_sync(0xffffffffu, d, 1);
            v += __shfl_xor_sync(0xffffffffu, v, 2);
            d += __shfl_xor_sync(0xffffffffu, d, 2);
            float F = v - 1.0f;
            if (fabsf(F) < 1e-6f) conv = true;
            float den = -2.0f * d;
            den = (den == 0.0f) ? 1.0f : den;
            if (!conv) s -= __fdividef(F, den);
        }

        float cH = -L2E * s;                      // e^{-r s} = 2^{r*cH}
        #pragma unroll
        for (int j = 0; j < 16; j += 2) {
            float xs0 = X[j]     * ex2f(R[j]     * cH);
            float xs1 = X[j + 1] * ex2f(R[j + 1] * cH);
            *(uint32_t*)(sm + OFF_XS + U4(m, (cb + j) >> 1, 32)) = packh(xs0, xs1);
        }
        if ((lane & 3) == 0) esclp[m] = ex2f(L2E * s);
    }
    __syncthreads();

    const int g  = lane >> 2;
    const int tg = lane & 3;
    const int mw = wid & 1;      // 2 M tiles of 32
    const int nw = wid >> 1;     // 4 N tiles (32 cols each per GEMM1 pass)

    const int lr  = lane & 7, seg = lane >> 3;
    const int arow = mw * 32 + lr + ((seg & 1) << 3);
    const int apo  = (seg & 2) << 1;
    const int axor = (arow & 7) << 2;

    const uint4* Wf1 = (const uint4*)g_Wbuf;
    const uint4* Wf2 = (const uint4*)(g_Wbuf + 32768) + (wid >> 1) * 512;
    const __half2 z2 = __floats2half2_rn(0.0f, 0.0f);

    // ---- GEMM1: [64x256] = Xh[64x64] @ W1h^T, 2 N-passes, warp tile 32x32 ----
    #pragma unroll
    for (int npass = 0; npass < 2; ++npass) {
        const int c32 = npass * 4 + nw;                       // 32-col block 0..7
        const int slotbase = (c32 >> 1) * 16 + (c32 & 1) * 2; // W1 frag slot base

        float acc[2][4][4];
        #pragma unroll
        for (int mi = 0; mi < 2; ++mi)
            #pragma unroll
            for (int j = 0; j < 4; ++j)
                #pragma unroll
                for (int q = 0; q < 4; ++q) acc[mi][j][q] = 0.0f;

        const uint32_t aB = smb + OFF_XS + arow * 128;
        uint32_t a0[4], a1[4], a0n[4], a1n[4];
        uint4 q, qn;

        ldm_x4(a0, aB +        ((apo ^ axor) << 2));
        ldm_x4(a1, aB + 2048 + ((apo ^ axor) << 2));
        q = __ldg(Wf1 + (slotbase << 5) + lane);
        #pragma unroll
        for (int kb = 0; kb < 4; ++kb) {
            #pragma unroll
            for (int jj = 0; jj < 2; ++jj) {
                // prefetch next B frag (jj+1, or next kb's jj=0) and next A frags
                if (jj == 0) {
                    qn = __ldg(Wf1 + ((slotbase + kb * 4 + 1) << 5) + lane);
                } else if (kb < 3) {
                    qn = __ldg(Wf1 + ((slotbase + (kb + 1) * 4) << 5) + lane);
                    int kb2 = (kb + 1) * 8;
                    ldm_x4(a0n, aB +        (((kb2 + apo) ^ axor) << 2));
                    ldm_x4(a1n, aB + 2048 + (((kb2 + apo) ^ axor) << 2));
                }
                mma16816(acc[0][2*jj],     a0, q.x, q.y);
                mma16816(acc[1][2*jj],     a1, q.x, q.y);
                mma16816(acc[0][2*jj + 1], a0, q.z, q.w);
                mma16816(acc[1][2*jj + 1], a1, q.z, q.w);
                q = qn;
                if (jj == 1) { cp4(a0, a0n); cp4(a1, a1n); }
            }
        }

        // epilogue (this pass): +b1, relu in half2 -> H (swizzled [64][128 units])
        #pragma unroll
        for (int mi = 0; mi < 2; ++mi) {
            int r0 = mw * 32 + mi * 16 + g;
            #pragma unroll
            for (int j = 0; j < 4; ++j) {
                int col = c32 * 32 + j * 8 + 2 * tg;
                int p = col >> 1;
                __half2 bb = b1h2[p];
                __half2 h0 = __hmax2(__hadd2(__floats2half2_rn(acc[mi][j][0], acc[mi][j][1]), bb), z2);
                __half2 h1 = __hmax2(__hadd2(__floats2half2_rn(acc[mi][j][2], acc[mi][j][3]), bb), z2);
                *(__half2*)(sm + OFF_H + U4(r0,     p, 128)) = h0;
                *(__half2*)(sm + OFF_H + U4(r0 + 8, p, 128)) = h1;
            }
        }
    }
    __syncthreads();

    // ---- GEMM2: [64x64] = Hh[64x256] @ W2h^T, warp tile 32x16, pipelined ----
    float acc2[2][2][4];
    #pragma unroll
    for (int mi = 0; mi < 2; ++mi)
        #pragma unroll
        for (int j = 0; j < 2; ++j)
            #pragma unroll
            for (int q = 0; q < 4; ++q) acc2[mi][j][q] = 0.0f;

    {
        const uint32_t aB = smb + OFF_H + arow * 512;
        uint32_t a0[4], a1[4], a0n[4], a1n[4];
        uint4 q, qn;

        ldm_x4(a0, aB +        ((apo ^ axor) << 2));
        ldm_x4(a1, aB + 8192 + ((apo ^ axor) << 2));
        q = __ldg(Wf2 + lane);
        #pragma unroll
        for (int kb = 0; kb < 16; ++kb) {
            if (kb < 15) {
                int kb2 = (kb + 1) * 8;
                qn = __ldg(Wf2 + ((kb + 1) << 5) + lane);
                ldm_x4(a0n, aB +        (((kb2 + apo) ^ axor) << 2));
                ldm_x4(a1n, aB + 8192 + (((kb2 + apo) ^ axor) << 2));
            }
            mma16816(acc2[0][0], a0, q.x, q.y);
            mma16816(acc2[1][0], a1, q.x, q.y);
            mma16816(acc2[0][1], a0, q.z, q.w);
            mma16816(acc2[1][1], a1, q.z, q.w);
            q = qn;
            cp4(a0, a0n); cp4(a1, a1n);
        }
    }

    // ---- epilogue2: +b2, * e^{s}, store ----
    #pragma unroll
    for (int mi = 0; mi < 2; ++mi) {
        int lr0 = mw * 32 + mi * 16 + g;
        int lr1 = lr0 + 8;
        float e0 = esclp[lr0], e1 = esclp[lr1];
        long long row0 = gb + lr0, row1 = gb + lr1;
        #pragma unroll
        for (int j = 0; j < 2; ++j) {
            int col = (wid >> 1) * 16 + j * 8 + 2 * tg;
            float bb0 = b2s[col], bb1 = b2s[col + 1];
            if (row0 < B)
                *(float2*)(out + row0 * 64 + col) =
                    make_float2((acc2[mi][j][0] + bb0) * e0, (acc2[mi][j][1] + bb1) * e0);
            if (row1 < B)
                *(float2*)(out + row1 * 64 + col) =
                    make_float2((acc2[mi][j][2] + bb0) * e1, (acc2[mi][j][3] + bb1) * e1);
        }
    }
}

extern "C" void kernel_launch(void* const* d_in, const int* in_sizes, int n_in,
                              void* d_out, int out_size) {
    const float* x  = (const float*)d_in[0];
    const float* r  = (const float*)d_in[1];
    const float* W1 = (const float*)d_in[2];
    const float* b1 = (const float*)d_in[3];
    const float* W2 = (const float*)d_in[4];
    const float* b2 = (const float*)d_in[5];
    float* out = (float*)d_out;

    const int B = in_sizes[0] / 64;
    const int grid = (B + TILE_B - 1) / TILE_B;

    prep_w_kernel<<<8, 256>>>(W1, W2);   // exactly 2048 threads = 2048 uint4 per half

    cudaFuncSetAttribute(aniso_mma_kernel,
                         cudaFuncAttributeMaxDynamicSharedMemorySize, SMEM_BYTES);
    aniso_mma_kernel<<<grid, THREADS, SMEM_BYTES>>>(x, r, b1, b2, out, B);
}

// round 16
// speedup vs baseline: 13.8258x; 1.0248x over previous
#include <cuda_runtime.h>
#include <cuda_fp16.h>
#include <cstdint>

#define THREADS 256
#define TILE_B  64

// ---------------- smem byte map (per CTA, 4 CTAs/SM) ----------------
#define OFF_XS  0          // Xs hi [64][64] f16, swizzled        8192
#define OFF_H   8192       // H hi  [64][256] f16                32768
#define OFF_ES  40960      // escl 64 f32                          256
#define OFF_B1  41216      // b1 as half2 [128]                    512
#define OFF_B2  41728      // b2   64 f32                          256
#define SMEM_BYTES 41984

// Swizzled byte offset of 4B unit (row, p); c2 = units per row. XOR at 16B
// granularity -> ldmatrix-legal rows, conflict-free phases.
#define U4(row, p, c2) ((((row) * (c2)) + ((p) ^ (((row) & 7) << 2))) << 2)

// W in mma B-FRAGMENT order (one uint4 per lane per 16x16 tile):
//   [0,32KB):  W1 frags, slot(nw,kb,jj) = nw*16 + kb*4 + jj   (nw,kb,jj in 0..3)
//   [32,64KB): W2 frags, slot(nw,kb)    = nw*16 + kb          (nw 0..3, kb 0..15)
// Per slot: 32 lanes x uint4 = {n0+g:(k,k+1), n0+g:(k+8,k+9), n0+8+g:(k,k+1), n0+8+g:(k+8,k+9)}
// 64 slots/half x 32 lanes = 2048 uint4 per half -> prep MUST use exactly 2048 threads.
__device__ __align__(16) unsigned char g_Wbuf[65536];

__device__ __forceinline__ float ex2f(float v) {
    float y; asm("ex2.approx.f32 %0, %1;" : "=f"(y) : "f"(v)); return y;
}
__device__ __forceinline__ float lg2f(float v) {
    float y; asm("lg2.approx.f32 %0, %1;" : "=f"(y) : "f"(v)); return y;
}
__device__ __forceinline__ uint32_t packh(float lo, float hi) {
    half2 h = __floats2half2_rn(lo, hi);          // lo -> low 16 bits
    return *(uint32_t*)&h;
}
__device__ __forceinline__ void mma16816(float* c, const uint32_t* a, uint32_t b0, uint32_t b1) {
    asm volatile(
        "mma.sync.aligned.m16n8k16.row.col.f32.f16.f16.f32 "
        "{%0,%1,%2,%3}, {%4,%5,%6,%7}, {%8,%9}, {%0,%1,%2,%3};"
        : "+f"(c[0]), "+f"(c[1]), "+f"(c[2]), "+f"(c[3])
        : "r"(a[0]), "r"(a[1]), "r"(a[2]), "r"(a[3]), "r"(b0), "r"(b1));
}
__device__ __forceinline__ void ldm_x4(uint32_t* d, uint32_t addr) {
    asm volatile("ldmatrix.sync.aligned.m8n8.x4.shared.b16 {%0,%1,%2,%3}, [%4];"
        : "=r"(d[0]), "=r"(d[1]), "=r"(d[2]), "=r"(d[3]) : "r"(addr));
}

// ---------------- prep kernel: W fp32 -> fp16 B-fragments (2048 threads!) ----
__global__ void prep_w_kernel(const float* __restrict__ W1, const float* __restrict__ W2) {
    int idx = blockIdx.x * 256 + threadIdx.x;     // 0..2047 (one per uint4 slot-entry)
    int lane = idx & 31, g = lane >> 2, tg = lane & 3;
    {   // W1 [256 n][64 k] -> frag slots (nw,kb,jj)
        int jj = (idx >> 5) & 3, kb = (idx >> 7) & 3, nw = (idx >> 9) & 3;
        int n = nw * 64 + jj * 16 + g;
        int k = kb * 16 + 2 * tg;
        uint4 v;
        v.x = packh(W1[n * 64 + k],           W1[n * 64 + k + 1]);
        v.y = packh(W1[n * 64 + k + 8],       W1[n * 64 + k + 9]);
        v.z = packh(W1[(n + 8) * 64 + k],     W1[(n + 8) * 64 + k + 1]);
        v.w = packh(W1[(n + 8) * 64 + k + 8], W1[(n + 8) * 64 + k + 9]);
        ((uint4*)g_Wbuf)[idx] = v;
    }
    {   // W2 [64 n][256 k] -> frag slots (nw,kb)
        int kb = (idx >> 5) & 15, nw = (idx >> 9) & 3;
        int n = nw * 16 + g;
        int k = kb * 16 + 2 * tg;
        uint4 v;
        v.x = packh(W2[n * 256 + k],           W2[n * 256 + k + 1]);
        v.y = packh(W2[n * 256 + k + 8],       W2[n * 256 + k + 9]);
        v.z = packh(W2[(n + 8) * 256 + k],     W2[(n + 8) * 256 + k + 1]);
        v.w = packh(W2[(n + 8) * 256 + k + 8], W2[(n + 8) * 256 + k + 9]);
        ((uint4*)(g_Wbuf + 32768))[idx] = v;
    }
}

__global__ __launch_bounds__(THREADS, 4)
void aniso_mma_kernel(const float* __restrict__ x, const float* __restrict__ r,
                      const float* __restrict__ b1, const float* __restrict__ b2,
                      float* __restrict__ out, int B)
{
    extern __shared__ char sm[];
    uint32_t smb;
    asm("{ .reg .u64 t; cvta.to.shared.u64 t, %1; cvt.u32.u64 %0, t; }" : "=r"(smb) : "l"(sm));
    float*  esclp = (float*)(sm + OFF_ES);
    __half2* b1h2 = (__half2*)(sm + OFF_B1);
    float*  b2s   = (float*)(sm + OFF_B2);

    const int tid  = threadIdx.x;
    const int lane = tid & 31;
    const int wid  = tid >> 5;
    const long long gb = (long long)blockIdx.x * TILE_B;

    if (tid < 128) b1h2[tid] = __floats2half2_rn(b1[2 * tid], b1[2 * tid + 1]);
    if (tid < 64)  b2s[tid] = b2[tid];

    // ---- log-domain Newton: 4-lane group per sample ----
    // phi(s) = ln(sum e^{-2 r s} x^2) is convex & decreasing; Newton on phi from
    // s=0 lands left of the root every step (tangent below convex curve), and
    // from s=0 the first step IS the old warm start. Freeze at |F| < 1e-6.
    {
        const float L2E = 1.4426950408889634f;
        const int sg = lane >> 2;
        const int cb = (lane & 3) << 4;
        const int m  = wid * 8 + sg;              // 0..63
        long long row = gb + m; if (row >= B) row = B - 1;

        float X[16], R[16];
        #pragma unroll
        for (int q4 = 0; q4 < 4; ++q4) {
            float4 v = *(const float4*)(x + row * 64 + cb + q4 * 4);
            X[q4*4+0] = v.x; X[q4*4+1] = v.y; X[q4*4+2] = v.z; X[q4*4+3] = v.w;
            float4 rv = *(const float4*)(r + cb + q4 * 4);
            R[q4*4+0] = rv.x; R[q4*4+1] = rv.y; R[q4*4+2] = rv.z; R[q4*4+3] = rv.w;
        }

        float s = 0.0f;
        bool conv = false;
        for (int it = 0; it < 30; ++it) {
            if (__all_sync(0xffffffffu, conv)) break;
            float c = (-2.0f * L2E) * s;          // e^{-2 r s} = 2^{r*c}
            float v = 0.0f, d = 0.0f;
            #pragma unroll
            for (int j = 0; j < 16; ++j) {
                float t = ex2f(R[j] * c) * (X[j] * X[j]);
                v += t; d += R[j] * t;
            }
            v += __shfl_xor_sync(0xffffffffu, v, 1);
            d += __shfl_xor_sync(0xffffffffu, d, 1);
            v += __shfl_xor_sync(0xffffffffu, v, 2);
            d += __shfl_xor_sync(0xffffffffu, d, 2);
            if (v < 1e-20f) conv = true;                      // all-zero sample
            else if (fabsf(v - 1.0f) < 1e-6f) conv = true;    // frozen (ref sem.)
            float den = (2.0f * L2E) * d;
            den = (den == 0.0f) ? 1.0f : den;
            if (!conv) s += v * __fdividef(lg2f(v), den);     // log-Newton step
        }

        float cH = -L2E * s;                      // e^{-r s} = 2^{r*cH}
        #pragma unroll
        for (int j = 0; j < 16; j += 2) {
            float xs0 = X[j]     * ex2f(R[j]     * cH);
            float xs1 = X[j + 1] * ex2f(R[j + 1] * cH);
            *(uint32_t*)(sm + OFF_XS + U4(m, (cb + j) >> 1, 32)) = packh(xs0, xs1);
        }
        if ((lane & 3) == 0) esclp[m] = ex2f(L2E * s);
    }
    __syncthreads();

    const int g  = lane >> 2;
    const int tg = lane & 3;
    const int mw = wid & 1;      // 2 M tiles of 32
    const int nw = wid >> 1;     // 4 N tiles (32 cols each per GEMM1 pass)

    const int lr  = lane & 7, seg = lane >> 3;
    const int arow = mw * 32 + lr + ((seg & 1) << 3);
    const int apo  = (seg & 2) << 1;
    const int axor = (arow & 7) << 2;

    const uint4* Wf1 = (const uint4*)g_Wbuf;
    const uint4* Wf2 = (const uint4*)(g_Wbuf + 32768) + (wid >> 1) * 512;
    const __half2 z2 = __floats2half2_rn(0.0f, 0.0f);

    // ---- GEMM1: [64x256] = Xh[64x64] @ W1h^T, 2 N-passes, warp tile 32x32 ----
    #pragma unroll
    for (int npass = 0; npass < 2; ++npass) {
        const int c32 = npass * 4 + nw;                       // 32-col block 0..7
        const int slotbase = (c32 >> 1) * 16 + (c32 & 1) * 2; // W1 frag slot base

        float acc[2][4][4];
        #pragma unroll
        for (int mi = 0; mi < 2; ++mi)
            #pragma unroll
            for (int j = 0; j < 4; ++j)
                #pragma unroll
                for (int q = 0; q < 4; ++q) acc[mi][j][q] = 0.0f;

        const uint32_t aB = smb + OFF_XS + arow * 128;
        #pragma unroll
        for (int kb = 0; kb < 4; ++kb) {
            uint32_t a0[4], a1[4];
            int kb2 = kb * 8;
            ldm_x4(a0, aB +        (((kb2 + apo) ^ axor) << 2));
            ldm_x4(a1, aB + 2048 + (((kb2 + apo) ^ axor) << 2));
            #pragma unroll
            for (int jj = 0; jj < 2; ++jj) {
                uint4 q = __ldg(Wf1 + ((slotbase + kb * 4 + jj) << 5) + lane);
                mma16816(acc[0][2*jj],     a0, q.x, q.y);
                mma16816(acc[1][2*jj],     a1, q.x, q.y);
                mma16816(acc[0][2*jj + 1], a0, q.z, q.w);
                mma16816(acc[1][2*jj + 1], a1, q.z, q.w);
            }
        }

        // epilogue (this pass): +b1, relu in half2 -> H (swizzled [64][128 units])
        #pragma unroll
        for (int mi = 0; mi < 2; ++mi) {
            int r0 = mw * 32 + mi * 16 + g;
            #pragma unroll
            for (int j = 0; j < 4; ++j) {
                int col = c32 * 32 + j * 8 + 2 * tg;
                int p = col >> 1;
                __half2 bb = b1h2[p];
                __half2 h0 = __hmax2(__hadd2(__floats2half2_rn(acc[mi][j][0], acc[mi][j][1]), bb), z2);
                __half2 h1 = __hmax2(__hadd2(__floats2half2_rn(acc[mi][j][2], acc[mi][j][3]), bb), z2);
                *(__half2*)(sm + OFF_H + U4(r0,     p, 128)) = h0;
                *(__half2*)(sm + OFF_H + U4(r0 + 8, p, 128)) = h1;
            }
        }
    }
    __syncthreads();

    // ---- GEMM2: [64x64] = Hh[64x256] @ W2h^T, warp tile 32x16 ----
    float acc2[2][2][4];
    #pragma unroll
    for (int mi = 0; mi < 2; ++mi)
        #pragma unroll
        for (int j = 0; j < 2; ++j)
            #pragma unroll
            for (int q = 0; q < 4; ++q) acc2[mi][j][q] = 0.0f;

    {
        const uint32_t aB = smb + OFF_H + arow * 512;
        #pragma unroll 8
        for (int kb = 0; kb < 16; ++kb) {
            uint32_t a0[4], a1[4];
            int kb2 = kb * 8;
            uint4 q = __ldg(Wf2 + (kb << 5) + lane);
            ldm_x4(a0, aB +        (((kb2 + apo) ^ axor) << 2));
            ldm_x4(a1, aB + 8192 + (((kb2 + apo) ^ axor) << 2));
            mma16816(acc2[0][0], a0, q.x, q.y);
            mma16816(acc2[1][0], a1, q.x, q.y);
            mma16816(acc2[0][1], a0, q.z, q.w);
            mma16816(acc2[1][1], a1, q.z, q.w);
        }
    }

    // ---- epilogue2: +b2, * e^{s}, store ----
    #pragma unroll
    for (int mi = 0; mi < 2; ++mi) {
        int lr0 = mw * 32 + mi * 16 + g;
        int lr1 = lr0 + 8;
        float e0 = esclp[lr0], e1 = esclp[lr1];
        long long row0 = gb + lr0, row1 = gb + lr1;
        #pragma unroll
        for (int j = 0; j < 2; ++j) {
            int col = (wid >> 1) * 16 + j * 8 + 2 * tg;
            float bb0 = b2s[col], bb1 = b2s[col + 1];
            if (row0 < B)
                *(float2*)(out + row0 * 64 + col) =
                    make_float2((acc2[mi][j][0] + bb0) * e0, (acc2[mi][j][1] + bb1) * e0);
            if (row1 < B)
                *(float2*)(out + row1 * 64 + col) =
                    make_float2((acc2[mi][j][2] + bb0) * e1, (acc2[mi][j][3] + bb1) * e1);
        }
    }
}

extern "C" void kernel_launch(void* const* d_in, const int* in_sizes, int n_in,
                              void* d_out, int out_size) {
    const float* x  = (const float*)d_in[0];
    const float* r  = (const float*)d_in[1];
    const float* W1 = (const float*)d_in[2];
    const float* b1 = (const float*)d_in[3];
    const float* W2 = (const float*)d_in[4];
    const float* b2 = (const float*)d_in[5];
    float* out = (float*)d_out;

    const int B = in_sizes[0] / 64;
    const int grid = (B + TILE_B - 1) / TILE_B;

    prep_w_kernel<<<8, 256>>>(W1, W2);   // exactly 2048 threads = 2048 uint4 per half

    cudaFuncSetAttribute(aniso_mma_kernel,
                         cudaFuncAttributeMaxDynamicSharedMemorySize, SMEM_BYTES);
    aniso_mma_kernel<<<grid, THREADS, SMEM_BYTES>>>(x, r, b1, b2, out, B);
}